// round 5
// baseline (speedup 1.0000x reference)
#include <cuda_runtime.h>
#include <cstdint>
#include <cstddef>

// ---------------------------------------------------------------------------
// SemRelAttention FP32 pipeline:
//   1) dw3x3(x, dw1)                  -> g_y1
//   2) gemm pw1 (768x256) @ y1        -> g_qkv   (B,768,128,128)
//   3) pool 8x8 max on k,v channels   -> g_kT/g_vT (head layout, d contiguous)
//   4) transpose q                    -> g_qT    (b,head,p,d)
//   5) attention (+rel bias, softmax) -> attn region of d_out + y2 (=g_y1)
//   6) dw3x3(y2, dw2)                 -> y3 (= head of g_qkv)
//   7) gemm pw2 (256x256) @ y3        -> out region of d_out
// d_out = [ out : 4*256*128*128 | attn : 4*4*16384*256 ]  fp32
//
// Scratch aliasing: y2 == g_y1 (y1 dead after step 2),
//                   y3 == g_qkv[0:67MB] (qkv dead after steps 3,4).
// ---------------------------------------------------------------------------

#define BATCH     4
#define CH        256
#define HW        16384     // 128*128
#define HEADS     4
#define DHEAD     64
#define NKEY      256       // 16*16
#define OUT_ELEMS (BATCH * CH * HW)          // 16777216

// ---------------- scratch (device globals, no allocation) ------------------
__device__ float g_y1[BATCH * CH * HW];              // 67 MB  (y1, then y2)
__device__ float g_qkv[BATCH * 3 * CH * HW];         // 201 MB (qkv, head reused as y3)
__device__ float g_qT[BATCH * HEADS * HW * DHEAD];   // 67 MB
__device__ float g_kT[BATCH * HEADS * NKEY * DHEAD]; // 1 MB
__device__ float g_vT[BATCH * HEADS * NKEY * DHEAD]; // 1 MB

// ---------------- depthwise 3x3, pad 1, C=256, float4 per thread ------------
__device__ __forceinline__ void dw3x3_body(const float* __restrict__ in,
                                           const float* __restrict__ wt,
                                           float* __restrict__ out) {
    int idx = blockIdx.x * 256 + threadIdx.x;   // OUT_ELEMS/4 threads
    int x4 = (idx & 31) << 2;                   // 0,4,...,124
    int y  = (idx >> 5) & 127;
    int bc = idx >> 12;                         // b*256 + c
    int c  = bc & 255;
    const float* wp = wt + c * 9;
    const float* ip = in + ((size_t)bc << 14);
    float4 acc = make_float4(0.f, 0.f, 0.f, 0.f);
#pragma unroll
    for (int dy = 0; dy < 3; dy++) {
        int yy = y + dy - 1;
        if (yy < 0 || yy > 127) continue;
        const float* rp = ip + (yy << 7);
        float4 cc = *reinterpret_cast<const float4*>(rp + x4);
        float lf = (x4 > 0)   ? rp[x4 - 1] : 0.f;   // zero-pad
        float rt = (x4 < 124) ? rp[x4 + 4] : 0.f;
        float a = wp[dy * 3], b = wp[dy * 3 + 1], cw = wp[dy * 3 + 2];
        acc.x += a * lf   + b * cc.x + cw * cc.y;
        acc.y += a * cc.x + b * cc.y + cw * cc.z;
        acc.z += a * cc.y + b * cc.z + cw * cc.w;
        acc.w += a * cc.z + b * cc.w + cw * rt;
    }
    *reinterpret_cast<float4*>(out + ((size_t)idx << 2)) = acc;
}

__global__ __launch_bounds__(256) void dw3x3_k1(const float* __restrict__ x,
                                                const float* __restrict__ dw1) {
    dw3x3_body(x, dw1, g_y1);
}
__global__ __launch_bounds__(256) void dw3x3_k2(const float* __restrict__ dw2) {
    dw3x3_body(g_y1 /*y2*/, dw2, g_qkv /*y3*/);
}

// ---------------- pointwise conv as batched GEMM ----------------------------
// C[z,m,n] = sum_k A[m,k] * B[z,k,n]; M%128==0, N%128==0, K%8==0
__device__ __forceinline__ void gemm128_body(const float* __restrict__ A,
                                             const float* __restrict__ B,
                                             float* __restrict__ C,
                                             int M, int N, int K) {
    __shared__ float As[8 * 128];
    __shared__ float Bs[8 * 128];
    const float* Bb = B + (size_t)blockIdx.z * K * N;
    float* Cb = C + (size_t)blockIdx.z * M * N;
    int tid = threadIdx.x;
    int tx = tid & 15, ty = tid >> 4;
    int m0 = blockIdx.y * 128, n0 = blockIdx.x * 128;
    float acc[8][8];
#pragma unroll
    for (int i = 0; i < 8; i++)
#pragma unroll
        for (int j = 0; j < 8; j++) acc[i][j] = 0.f;

    for (int kk = 0; kk < K; kk += 8) {
        {   // A tile: 128 m x 8 k (transposed into smem)
            int m = tid >> 1, k0 = (tid & 1) * 4;
            float4 a = *reinterpret_cast<const float4*>(&A[(size_t)(m0 + m) * K + kk + k0]);
            As[(k0 + 0) * 128 + m] = a.x;
            As[(k0 + 1) * 128 + m] = a.y;
            As[(k0 + 2) * 128 + m] = a.z;
            As[(k0 + 3) * 128 + m] = a.w;
        }
        {   // B tile: 8 k x 128 n, coalesced float4
            int k = tid >> 5, n = (tid & 31) * 4;
            *reinterpret_cast<float4*>(&Bs[k * 128 + n]) =
                *reinterpret_cast<const float4*>(&Bb[(size_t)(kk + k) * N + n0 + n]);
        }
        __syncthreads();
#pragma unroll
        for (int k = 0; k < 8; k++) {
            float a[8], bb[8];
            *reinterpret_cast<float4*>(a)      = *reinterpret_cast<const float4*>(&As[k * 128 + ty * 8]);
            *reinterpret_cast<float4*>(a + 4)  = *reinterpret_cast<const float4*>(&As[k * 128 + ty * 8 + 4]);
            *reinterpret_cast<float4*>(bb)     = *reinterpret_cast<const float4*>(&Bs[k * 128 + tx * 8]);
            *reinterpret_cast<float4*>(bb + 4) = *reinterpret_cast<const float4*>(&Bs[k * 128 + tx * 8 + 4]);
#pragma unroll
            for (int i = 0; i < 8; i++)
#pragma unroll
                for (int j = 0; j < 8; j++) acc[i][j] += a[i] * bb[j];
        }
        __syncthreads();
    }
#pragma unroll
    for (int i = 0; i < 8; i++) {
        float* cp = &Cb[(size_t)(m0 + ty * 8 + i) * N + n0 + tx * 8];
        *reinterpret_cast<float4*>(cp)     = *reinterpret_cast<float4*>(&acc[i][0]);
        *reinterpret_cast<float4*>(cp + 4) = *reinterpret_cast<float4*>(&acc[i][4]);
    }
}

__global__ __launch_bounds__(256) void gemm_pw1(const float* __restrict__ pw1) {
    gemm128_body(pw1, g_y1, g_qkv, 768, HW, 256);
}
__global__ __launch_bounds__(256) void gemm_pw2(const float* __restrict__ pw2,
                                                float* __restrict__ out) {
    gemm128_body(pw2, g_qkv /*y3*/, out, 256, HW, 256);
}

// ---------------- 8x8 max pool of k,v + head-layout transpose ---------------
// kT/vT[((b*4+head)*256 + hk*16+wk)*64 + d],  c = d*4 + head
__global__ __launch_bounds__(256) void pool_kv() {
    int idx = blockIdx.x * 256 + threadIdx.x;   // 2*B*256*16*16 = 524288
    int wk = idx & 15;
    int hk = (idx >> 4) & 15;
    int c = (idx >> 8) & 255;
    int which = (idx >> 16) & 1;
    int b = idx >> 17;
    int ch = 256 + which * 256 + c;
    const float* src = g_qkv + (((size_t)(b * 768 + ch)) << 14) + ((hk * 8) << 7) + wk * 8;
    float m = -3.402823466e+38f;
#pragma unroll
    for (int dy = 0; dy < 8; dy++)
#pragma unroll
        for (int dx = 0; dx < 8; dx++)
            m = fmaxf(m, src[(dy << 7) + dx]);
    int head = c & 3, d = c >> 2;
    size_t dst = (((size_t)(b * HEADS + head)) * NKEY + (hk * 16 + wk)) * DHEAD + d;
    if (which == 0) g_kT[dst] = m; else g_vT[dst] = m;
}

// ---------------- q transpose to (b,head,p,d), d contiguous -----------------
__global__ __launch_bounds__(256) void transpose_q() {
    __shared__ float tile[64 * 65];
    int bx = blockIdx.x;                 // 4*4*256 blocks
    int p0 = (bx & 255) << 6;
    int head = (bx >> 8) & 3;
    int b = bx >> 10;
    int t = threadIdx.x;
#pragma unroll
    for (int i = 0; i < 16; i++) {
        int idx = i * 256 + t;
        int d = idx >> 6, p = idx & 63;
        tile[d * 65 + p] = g_qkv[(((size_t)(b * 768 + d * 4 + head)) << 14) + p0 + p];
    }
    __syncthreads();
    size_t base = (((size_t)(b * HEADS + head)) << 14) + p0;
#pragma unroll
    for (int i = 0; i < 16; i++) {
        int idx = i * 256 + t;
        int p = idx >> 6, d = idx & 63;
        g_qT[(base + p) * 64 + d] = tile[d * 65 + p];
    }
}

// ---------------- fused attention + rel bias + softmax ----------------------
// grid (hq=128, head=4, b=4), 256 threads = 8 warps; warp owns 16 wq columns,
// processed 4 queries at a time (amortizes K smem traffic 4x).
#define ATTN_SMEM_FLOATS 57344
__global__ __launch_bounds__(256, 1) void attn_kernel(
    const float* __restrict__ relw, const float* __restrict__ relh,
    float* __restrict__ attn_out) {
    extern __shared__ float sm[];
    float* kS  = sm;            // 16384: blocked [d4][j][d&3]  (float4 / key)
    float* vS  = sm + 16384;    // 16384: [j][d]
    float* rwS = sm + 32768;    // 31*65 rows (padded)
    float* rhS = sm + 34784;
    float* qS  = sm + 36800;    // 8 warps * 4q * 64 (16B aligned)
    float* grw = sm + 38848;    // 8 * 4 * 32
    float* grh = sm + 39872;
    float* pS  = sm + 40896;    // 8 * 4 * 256
    float* oT  = sm + 49088;    // 64 * 129

    int hq = blockIdx.x, head = blockIdx.y, b = blockIdx.z;
    int t = threadIdx.x, lane = t & 31, w = t >> 5;

    size_t kvbase = ((size_t)(b * HEADS + head)) * (NKEY * DHEAD);
    for (int i = t; i < NKEY * DHEAD; i += 256) {
        int j = i >> 6, d = i & 63;
        kS[(d >> 2) * 1024 + j * 4 + (d & 3)] = g_kT[kvbase + i];
        vS[i] = g_vT[kvbase + i];
    }
    for (int i = t; i < 31 * 64; i += 256) {
        int m = i >> 6, d = i & 63;
        rwS[m * 65 + d] = relw[i];
        rhS[m * 65 + d] = relh[i];
    }
    __syncthreads();

    int hq8 = hq >> 3;
    size_t qbase = (((size_t)(b * HEADS + head)) * HW + (size_t)hq * 128) * DHEAD;
    size_t abase = (((size_t)(b * HEADS + head)) * HW + (size_t)hq * 128) * NKEY;

    for (int qg = 0; qg < 4; qg++) {
        int wq0 = w * 16 + qg * 4;
        // stage 4 q vectors for this warp
#pragma unroll
        for (int qq = 0; qq < 4; qq++) {
            qS[w * 256 + qq * 64 + lane]      = g_qT[qbase + (size_t)(wq0 + qq) * 64 + lane];
            qS[w * 256 + qq * 64 + lane + 32] = g_qT[qbase + (size_t)(wq0 + qq) * 64 + lane + 32];
        }
        __syncwarp();
        // rel-pos logits: lane m<31 computes q . key_rel_{w,h}[m] per query
        if (lane < 31) {
#pragma unroll
            for (int qq = 0; qq < 4; qq++) {
                float aw = 0.f, ah = 0.f;
#pragma unroll 8
                for (int d = 0; d < 64; d++) {
                    float qv = qS[w * 256 + qq * 64 + d];
                    aw += qv * rwS[lane * 65 + d];
                    ah += qv * rhS[lane * 65 + d];
                }
                grw[w * 128 + qq * 32 + lane] = aw;
                grh[w * 128 + qq * 32 + lane] = ah;
            }
        }
        __syncwarp();

        // q.k : 4 queries x 8 keys per lane
        float acc[4][8];
#pragma unroll
        for (int qq = 0; qq < 4; qq++)
#pragma unroll
            for (int u = 0; u < 8; u++) acc[qq][u] = 0.f;

#pragma unroll 4
        for (int d4 = 0; d4 < 16; d4++) {
            float4 qv[4];
#pragma unroll
            for (int qq = 0; qq < 4; qq++)
                qv[qq] = *reinterpret_cast<const float4*>(&qS[w * 256 + qq * 64 + d4 * 4]);
#pragma unroll
            for (int u = 0; u < 8; u++) {
                int j = u * 32 + lane;
                float4 kv = *reinterpret_cast<const float4*>(&kS[d4 * 1024 + j * 4]);
#pragma unroll
                for (int qq = 0; qq < 4; qq++)
                    acc[qq][u] += qv[qq].x * kv.x + qv[qq].y * kv.y
                                + qv[qq].z * kv.z + qv[qq].w * kv.w;
            }
        }

        // bias + softmax + attn writeout
#pragma unroll
        for (int qq = 0; qq < 4; qq++) {
            int wq = wq0 + qq, wq8 = wq >> 3;
            float sv[8], mx = -3.402823466e+38f;
#pragma unroll
            for (int u = 0; u < 8; u++) {
                int j = u * 32 + lane, hk = j >> 4, wk = j & 15;
                float xv = (acc[qq][u]
                            + grh[w * 128 + qq * 32 + hk - hq8 + 15]
                            + grw[w * 128 + qq * 32 + wk - wq8 + 15]) * 0.125f;
                sv[u] = xv;
                mx = fmaxf(mx, xv);
            }
#pragma unroll
            for (int o = 16; o > 0; o >>= 1)
                mx = fmaxf(mx, __shfl_xor_sync(0xffffffffu, mx, o));
            float sum = 0.f;
#pragma unroll
            for (int u = 0; u < 8; u++) { sv[u] = __expf(sv[u] - mx); sum += sv[u]; }
#pragma unroll
            for (int o = 16; o > 0; o >>= 1)
                sum += __shfl_xor_sync(0xffffffffu, sum, o);
            float inv = 1.f / sum;
#pragma unroll
            for (int u = 0; u < 8; u++) {
                float p = sv[u] * inv;
                attn_out[abase + (size_t)wq * 256 + u * 32 + lane] = p;
                pS[w * 1024 + qq * 256 + u * 32 + lane] = p;
            }
        }
        __syncwarp();

        // attn @ V : lane owns d = lane, lane+32 for the 4 queries
        float o0[4] = {0.f, 0.f, 0.f, 0.f}, o1[4] = {0.f, 0.f, 0.f, 0.f};
#pragma unroll 4
        for (int j = 0; j < 256; j++) {
            float v0 = vS[j * 64 + lane];
            float v1 = vS[j * 64 + lane + 32];
#pragma unroll
            for (int qq = 0; qq < 4; qq++) {
                float p = pS[w * 1024 + qq * 256 + j];
                o0[qq] += p * v0;
                o1[qq] += p * v1;
            }
        }
#pragma unroll
        for (int qq = 0; qq < 4; qq++) {
            oT[lane * 129 + wq0 + qq]        = o0[qq];
            oT[(lane + 32) * 129 + wq0 + qq] = o1[qq];
        }
        __syncwarp();
    }
    __syncthreads();
    // write row to channel layout y2 (== g_y1): [b, d*4+head, hq, x]
    for (int i = t; i < 64 * 128; i += 256) {
        int d = i >> 7, x = i & 127;
        g_y1[(((size_t)(b * CH + d * 4 + head)) * 128 + hq) * 128 + x] = oT[d * 129 + x];
    }
}

// ---------------------------------------------------------------------------
extern "C" void kernel_launch(void* const* d_in, const int* in_sizes, int n_in,
                              void* d_out, int out_size) {
    (void)in_sizes; (void)n_in; (void)out_size;
    const float* x    = (const float*)d_in[0];
    const float* dw1  = (const float*)d_in[1];
    const float* pw1  = (const float*)d_in[2];
    const float* relw = (const float*)d_in[3];
    const float* relh = (const float*)d_in[4];
    const float* dw2  = (const float*)d_in[5];
    const float* pw2  = (const float*)d_in[6];
    float* out  = (float*)d_out;
    float* attn = out + OUT_ELEMS;

    cudaFuncSetAttribute(attn_kernel, cudaFuncAttributeMaxDynamicSharedMemorySize,
                         ATTN_SMEM_FLOATS * 4);

    dw3x3_k1<<<OUT_ELEMS / 1024, 256>>>(x, dw1);
    gemm_pw1<<<dim3(128, 6, 4), 256>>>(pw1);
    pool_kv<<<2048, 256>>>();
    transpose_q<<<4096, 256>>>();
    attn_kernel<<<dim3(128, HEADS, BATCH), 256, ATTN_SMEM_FLOATS * 4>>>(relw, relh, attn);
    dw3x3_k2<<<OUT_ELEMS / 1024, 256>>>(dw2);
    gemm_pw2<<<dim3(128, 2, 4), 256>>>(pw2, out);
}

// round 8
// speedup vs baseline: 1.2797x; 1.2797x over previous
#include <cuda_runtime.h>
#include <cuda_bf16.h>
#include <cstdint>
#include <cstddef>

// ---------------------------------------------------------------------------
// SemRelAttention pipeline, HMMA (mma.sync bf16) split GEMMs for pw1/pw2:
//   0) convert_w : pw1/pw2 fp32 -> bf16 K-expanded A' = [Ah|Al|Ah] (K=768)
//   1) dw3x3(x, dw1)            -> g_y1
//   2) tconv(y1)                -> g_bT [n][512] = [Bh|Bl] bf16
//   3) gemm_mma pw1             -> g_qkv
//   4) pool 8x8 max k,v / transpose q
//   5) attention (+rel bias)    -> attn region + y2 (=g_y1)
//   6) dw3x3(y2, dw2)           -> y3 (= head of g_qkv)
//   7) tconv(y3)                -> g_bT
//   8) gemm_mma pw2             -> out region
// d_out = [ out : 4*256*128*128 | attn : 4*4*16384*256 ]  fp32
// GEMM K-stages: s in [0,24): A cols s*32 of [Ah|Al|Ah];
//   B cols (s<8 ? s*32 : (s-8)*32) of [Bh|Bl]  ->  AhBh + AlBh + AhBl.
// ---------------------------------------------------------------------------

#define BATCH     4
#define CH        256
#define HW        16384
#define HEADS     4
#define DHEAD     64
#define NKEY      256
#define NT_TOTAL  65536
#define OUT_ELEMS (BATCH * CH * HW)

// ---------------- scratch (device globals, no allocation) ------------------
__device__ float g_y1[BATCH * CH * HW];                // y1, then y2
__device__ float g_qkv[BATCH * 3 * CH * HW];           // qkv, head reused as y3
__device__ float g_qT[BATCH * HEADS * HW * DHEAD];
__device__ float g_kT[BATCH * HEADS * NKEY * DHEAD];
__device__ float g_vT[BATCH * HEADS * NKEY * DHEAD];
__device__ __align__(128) __nv_bfloat16 g_a1[768 * 768];            // [Ah|Al|Ah]
__device__ __align__(128) __nv_bfloat16 g_a2[256 * 768];
__device__ __align__(128) __nv_bfloat16 g_bT[(size_t)NT_TOTAL * 512]; // [Bh|Bl]

// ---------------- weight split fp32 -> bf16 K-expanded ----------------------
__global__ __launch_bounds__(256) void convert_w(const float* __restrict__ pw1,
                                                 const float* __restrict__ pw2) {
    int idx = blockIdx.x * 256 + threadIdx.x;      // 262144 total
    float f;
    if (idx < 768 * 256) f = pw1[idx]; else f = pw2[idx - 768 * 256];
    __nv_bfloat16 hi = __float2bfloat16_rn(f);
    __nv_bfloat16 lo = __float2bfloat16_rn(f - __bfloat162float(hi));
    if (idx < 768 * 256) {
        int m = idx >> 8, c = idx & 255;
        g_a1[m * 768 + c] = hi;
        g_a1[m * 768 + 256 + c] = lo;
        g_a1[m * 768 + 512 + c] = hi;
    } else {
        int r = idx - 768 * 256;
        int m = r >> 8, c = r & 255;
        g_a2[m * 768 + c] = hi;
        g_a2[m * 768 + 256 + c] = lo;
        g_a2[m * 768 + 512 + c] = hi;
    }
}

// ---------------- transpose + split: [b][c][pos] f32 -> [n][512] bf16 -------
__device__ __forceinline__ void tconv_body(const float* __restrict__ in) {
    __shared__ float tile[32][33];
    int p0 = blockIdx.x * 32, c0 = blockIdx.y * 32, b = blockIdx.z;
    int t = threadIdx.x;
    {
        int ci = t >> 3, pj = (t & 7) * 4;
        float4 v = *reinterpret_cast<const float4*>(
            in + (((size_t)(b * 256 + c0 + ci)) << 14) + p0 + pj);
        tile[ci][pj] = v.x; tile[ci][pj + 1] = v.y;
        tile[ci][pj + 2] = v.z; tile[ci][pj + 3] = v.w;
    }
    __syncthreads();
    {
        int pi = t >> 3, cj = (t & 7) * 4;
        size_t n = (size_t)b * HW + p0 + pi;
        uint32_t hp[2], lp[2];
#pragma unroll
        for (int u = 0; u < 2; u++) {
            float f0 = tile[cj + 2 * u][pi], f1 = tile[cj + 2 * u + 1][pi];
            __nv_bfloat16 h0 = __float2bfloat16_rn(f0);
            __nv_bfloat16 h1 = __float2bfloat16_rn(f1);
            __nv_bfloat16 l0 = __float2bfloat16_rn(f0 - __bfloat162float(h0));
            __nv_bfloat16 l1 = __float2bfloat16_rn(f1 - __bfloat162float(h1));
            hp[u] = (uint32_t)__bfloat16_as_ushort(h0) | ((uint32_t)__bfloat16_as_ushort(h1) << 16);
            lp[u] = (uint32_t)__bfloat16_as_ushort(l0) | ((uint32_t)__bfloat16_as_ushort(l1) << 16);
        }
        *reinterpret_cast<uint2*>(&g_bT[n * 512 + c0 + cj]) = make_uint2(hp[0], hp[1]);
        *reinterpret_cast<uint2*>(&g_bT[n * 512 + 256 + c0 + cj]) = make_uint2(lp[0], lp[1]);
    }
}
__global__ __launch_bounds__(256) void tconv_y1() { tconv_body(g_y1); }
__global__ __launch_bounds__(256) void tconv_y3() { tconv_body(g_qkv); }

// ======================= HMMA GEMM (mma.sync bf16) ==========================
// C[b][m][pos] = A'[m][0:768] @ B'[pos][·]; 128x128 tile per block,
// 256 threads = 4(m) x 2(n) warps, warp tile 32x64, k-stage 32, 24 stages.
#define SROW 40          // smem row stride in bf16 (80 B): 5r mod 8 -> conflict-free

__device__ __forceinline__ void cp16(uint32_t dst, const void* src) {
    asm volatile("{ .reg .u64 g; cvta.to.global.u64 g, %1; "
                 "cp.async.cg.shared.global [%0], [g], 16; }"
                 :: "r"(dst), "l"(src));
}
__device__ __forceinline__ void ldsm4(uint32_t* r, uint32_t a) {
    asm volatile("ldmatrix.sync.aligned.m8n8.x4.shared.b16 {%0,%1,%2,%3}, [%4];"
                 : "=r"(r[0]), "=r"(r[1]), "=r"(r[2]), "=r"(r[3]) : "r"(a));
}
__device__ __forceinline__ void mma16816(float* c, const uint32_t* a,
                                         uint32_t b0, uint32_t b1) {
    asm volatile("mma.sync.aligned.m16n8k16.row.col.f32.bf16.bf16.f32 "
                 "{%0,%1,%2,%3}, {%4,%5,%6,%7}, {%8,%9}, {%0,%1,%2,%3};"
                 : "+f"(c[0]), "+f"(c[1]), "+f"(c[2]), "+f"(c[3])
                 : "r"(a[0]), "r"(a[1]), "r"(a[2]), "r"(a[3]), "r"(b0), "r"(b1));
}

__device__ __forceinline__ void gemm_mma_body(const __nv_bfloat16* __restrict__ A,
                                              float* __restrict__ C) {
    __shared__ __align__(16) __nv_bfloat16 sA[2][128 * SROW];
    __shared__ __align__(16) __nv_bfloat16 sB[2][128 * SROW];
    int t = threadIdx.x, lane = t & 31, w = t >> 5;
    int wm = w >> 1, wn = w & 1;
    int nt = blockIdx.x, mtb = blockIdx.y;
    int Mrows = gridDim.y * 128;

    const __nv_bfloat16* Ab = A + (size_t)mtb * 128 * 768;
    const __nv_bfloat16* Bb = g_bT + (size_t)nt * 128 * 512;

    uint32_t sAb, sBb;
    asm("{ .reg .u64 t; cvta.to.shared.u64 t, %1; cvt.u32.u64 %0, t; }" : "=r"(sAb) : "l"(&sA[0][0]));
    asm("{ .reg .u64 t; cvta.to.shared.u64 t, %1; cvt.u32.u64 %0, t; }" : "=r"(sBb) : "l"(&sB[0][0]));

    // per-thread load coords: 2 x (row, 16B chunk) for A and B
    int lrow0 = t >> 2,            lc0 = (t & 3) * 8;
    int lrow1 = (256 + t) >> 2,    lc1 = lc0;   // same chunk col, rows 64..127

    float acc[2][8][4];
#pragma unroll
    for (int i = 0; i < 2; i++)
#pragma unroll
        for (int j = 0; j < 8; j++)
#pragma unroll
            for (int q = 0; q < 4; q++) acc[i][j][q] = 0.f;

    auto stage_load = [&](int s, int buf) {
        int ao = s * 32;
        int bo = (s < 8) ? s * 32 : (s - 8) * 32;
        uint32_t da = sAb + buf * (128 * SROW * 2);
        uint32_t db = sBb + buf * (128 * SROW * 2);
        cp16(da + (lrow0 * SROW + lc0) * 2, Ab + (size_t)lrow0 * 768 + ao + lc0);
        cp16(da + (lrow1 * SROW + lc1) * 2, Ab + (size_t)lrow1 * 768 + ao + lc1);
        cp16(db + (lrow0 * SROW + lc0) * 2, Bb + (size_t)lrow0 * 512 + bo + lc0);
        cp16(db + (lrow1 * SROW + lc1) * 2, Bb + (size_t)lrow1 * 512 + bo + lc1);
        asm volatile("cp.async.commit_group;" ::: "memory");
    };

    stage_load(0, 0);
    for (int s = 0; s < 24; s++) {
        int buf = s & 1;
        if (s + 1 < 24) {
            stage_load(s + 1, buf ^ 1);
            asm volatile("cp.async.wait_group 1;" ::: "memory");
        } else {
            asm volatile("cp.async.wait_group 0;" ::: "memory");
        }
        __syncthreads();
        uint32_t aB = sAb + buf * (128 * SROW * 2);
        uint32_t bB = sBb + buf * (128 * SROW * 2);
#pragma unroll
        for (int k16 = 0; k16 < 2; k16++) {
            uint32_t af[2][4];
#pragma unroll
            for (int mt = 0; mt < 2; mt++) {
                int row = wm * 32 + mt * 16 + (lane & 15);
                int col = k16 * 16 + (lane >> 4) * 8;
                ldsm4(af[mt], aB + (row * SROW + col) * 2);
            }
            uint32_t bf[4][4];
#pragma unroll
            for (int nq = 0; nq < 4; nq++) {
                int n = wn * 64 + nq * 16 + ((lane >> 4) << 3) + (lane & 7);
                int kc = k16 * 16 + ((lane >> 3) & 1) * 8;
                ldsm4(bf[nq], bB + (n * SROW + kc) * 2);
            }
#pragma unroll
            for (int mt = 0; mt < 2; mt++)
#pragma unroll
                for (int nq = 0; nq < 4; nq++) {
                    mma16816(acc[mt][nq * 2],     af[mt], bf[nq][0], bf[nq][1]);
                    mma16816(acc[mt][nq * 2 + 1], af[mt], bf[nq][2], bf[nq][3]);
                }
        }
        __syncthreads();
    }

    // epilogue: direct stores (32B sectors fully used)
    int b = nt >> 7;
    int n0 = (nt & 127) * 128;
    size_t base = (size_t)b * Mrows * HW + (size_t)mtb * 128 * HW + n0;
#pragma unroll
    for (int mt = 0; mt < 2; mt++) {
        int row0 = wm * 32 + mt * 16 + (lane >> 2);
#pragma unroll
        for (int nq = 0; nq < 8; nq++) {
            int col = wn * 64 + nq * 8 + (lane & 3) * 2;
            float* p0 = &C[base + (size_t)row0 * HW + col];
            float* p1 = &C[base + (size_t)(row0 + 8) * HW + col];
            *reinterpret_cast<float2*>(p0) = make_float2(acc[mt][nq][0], acc[mt][nq][1]);
            *reinterpret_cast<float2*>(p1) = make_float2(acc[mt][nq][2], acc[mt][nq][3]);
        }
    }
}

__global__ __launch_bounds__(256) void gemm_mma_pw1() { gemm_mma_body(g_a1, g_qkv); }
__global__ __launch_bounds__(256) void gemm_mma_pw2(float* __restrict__ out) {
    gemm_mma_body(g_a2, out);
}

// ---------------- depthwise 3x3, pad 1, float4 per thread -------------------
__device__ __forceinline__ void dw3x3_body(const float* __restrict__ in,
                                           const float* __restrict__ wt,
                                           float* __restrict__ out) {
    int idx = blockIdx.x * 256 + threadIdx.x;
    int x4 = (idx & 31) << 2;
    int y  = (idx >> 5) & 127;
    int bc = idx >> 12;
    int c  = bc & 255;
    const float* wp = wt + c * 9;
    const float* ip = in + ((size_t)bc << 14);
    float4 acc = make_float4(0.f, 0.f, 0.f, 0.f);
#pragma unroll
    for (int dy = 0; dy < 3; dy++) {
        int yy = y + dy - 1;
        if (yy < 0 || yy > 127) continue;
        const float* rp = ip + (yy << 7);
        float4 cc = *reinterpret_cast<const float4*>(rp + x4);
        float lf = (x4 > 0)   ? rp[x4 - 1] : 0.f;
        float rt = (x4 < 124) ? rp[x4 + 4] : 0.f;
        float a = wp[dy * 3], b = wp[dy * 3 + 1], cw = wp[dy * 3 + 2];
        acc.x += a * lf   + b * cc.x + cw * cc.y;
        acc.y += a * cc.x + b * cc.y + cw * cc.z;
        acc.z += a * cc.y + b * cc.z + cw * cc.w;
        acc.w += a * cc.z + b * cc.w + cw * rt;
    }
    *reinterpret_cast<float4*>(out + ((size_t)idx << 2)) = acc;
}
__global__ __launch_bounds__(256) void dw3x3_k1(const float* __restrict__ x,
                                                const float* __restrict__ dw1) {
    dw3x3_body(x, dw1, g_y1);
}
__global__ __launch_bounds__(256) void dw3x3_k2(const float* __restrict__ dw2) {
    dw3x3_body(g_y1, dw2, g_qkv);
}

// ---------------- 8x8 max pool of k,v + head-layout transpose ---------------
__global__ __launch_bounds__(256) void pool_kv() {
    int idx = blockIdx.x * 256 + threadIdx.x;
    int wk = idx & 15;
    int hk = (idx >> 4) & 15;
    int c = (idx >> 8) & 255;
    int which = (idx >> 16) & 1;
    int b = idx >> 17;
    int ch = 256 + which * 256 + c;
    const float* src = g_qkv + (((size_t)(b * 768 + ch)) << 14) + ((hk * 8) << 7) + wk * 8;
    float m = -3.402823466e+38f;
#pragma unroll
    for (int dy = 0; dy < 8; dy++)
#pragma unroll
        for (int dx = 0; dx < 8; dx++)
            m = fmaxf(m, src[(dy << 7) + dx]);
    int head = c & 3, d = c >> 2;
    size_t dst = (((size_t)(b * HEADS + head)) * NKEY + (hk * 16 + wk)) * DHEAD + d;
    if (which == 0) g_kT[dst] = m; else g_vT[dst] = m;
}

// ---------------- q transpose to (b,head,p,d) -------------------------------
__global__ __launch_bounds__(256) void transpose_q() {
    __shared__ float tile[64 * 65];
    int bx = blockIdx.x;
    int p0 = (bx & 255) << 6;
    int head = (bx >> 8) & 3;
    int b = bx >> 10;
    int t = threadIdx.x;
#pragma unroll
    for (int i = 0; i < 16; i++) {
        int idx = i * 256 + t;
        int d = idx >> 6, p = idx & 63;
        tile[d * 65 + p] = g_qkv[(((size_t)(b * 768 + d * 4 + head)) << 14) + p0 + p];
    }
    __syncthreads();
    size_t base = (((size_t)(b * HEADS + head)) << 14) + p0;
#pragma unroll
    for (int i = 0; i < 16; i++) {
        int idx = i * 256 + t;
        int p = idx >> 6, d = idx & 63;
        g_qT[(base + p) * 64 + d] = tile[d * 65 + p];
    }
}

// ---------------- fused attention + rel bias + softmax ----------------------
#define ATTN_SMEM_FLOATS 57344
__global__ __launch_bounds__(256, 1) void attn_kernel(
    const float* __restrict__ relw, const float* __restrict__ relh,
    float* __restrict__ attn_out) {
    extern __shared__ float sm[];
    float* kS  = sm;
    float* vS  = sm + 16384;
    float* rwS = sm + 32768;
    float* rhS = sm + 34784;
    float* qS  = sm + 36800;
    float* grw = sm + 38848;
    float* grh = sm + 39872;
    float* pS  = sm + 40896;
    float* oT  = sm + 49088;

    int hq = blockIdx.x, head = blockIdx.y, b = blockIdx.z;
    int t = threadIdx.x, lane = t & 31, w = t >> 5;

    size_t kvbase = ((size_t)(b * HEADS + head)) * (NKEY * DHEAD);
    for (int i = t; i < NKEY * DHEAD; i += 256) {
        int j = i >> 6, d = i & 63;
        kS[(d >> 2) * 1024 + j * 4 + (d & 3)] = g_kT[kvbase + i];
        vS[i] = g_vT[kvbase + i];
    }
    for (int i = t; i < 31 * 64; i += 256) {
        int m = i >> 6, d = i & 63;
        rwS[m * 65 + d] = relw[i];
        rhS[m * 65 + d] = relh[i];
    }
    __syncthreads();

    int hq8 = hq >> 3;
    size_t qbase = (((size_t)(b * HEADS + head)) * HW + (size_t)hq * 128) * DHEAD;
    size_t abase = (((size_t)(b * HEADS + head)) * HW + (size_t)hq * 128) * NKEY;

    for (int qg = 0; qg < 4; qg++) {
        int wq0 = w * 16 + qg * 4;
#pragma unroll
        for (int qq = 0; qq < 4; qq++) {
            qS[w * 256 + qq * 64 + lane]      = g_qT[qbase + (size_t)(wq0 + qq) * 64 + lane];
            qS[w * 256 + qq * 64 + lane + 32] = g_qT[qbase + (size_t)(wq0 + qq) * 64 + lane + 32];
        }
        __syncwarp();
        if (lane < 31) {
#pragma unroll
            for (int qq = 0; qq < 4; qq++) {
                float aw = 0.f, ah = 0.f;
#pragma unroll 8
                for (int d = 0; d < 64; d++) {
                    float qv = qS[w * 256 + qq * 64 + d];
                    aw += qv * rwS[lane * 65 + d];
                    ah += qv * rhS[lane * 65 + d];
                }
                grw[w * 128 + qq * 32 + lane] = aw;
                grh[w * 128 + qq * 32 + lane] = ah;
            }
        }
        __syncwarp();

        float acc[4][8];
#pragma unroll
        for (int qq = 0; qq < 4; qq++)
#pragma unroll
            for (int u = 0; u < 8; u++) acc[qq][u] = 0.f;

#pragma unroll 4
        for (int d4 = 0; d4 < 16; d4++) {
            float4 qv[4];
#pragma unroll
            for (int qq = 0; qq < 4; qq++)
                qv[qq] = *reinterpret_cast<const float4*>(&qS[w * 256 + qq * 64 + d4 * 4]);
#pragma unroll
            for (int u = 0; u < 8; u++) {
                int j = u * 32 + lane;
                float4 kv = *reinterpret_cast<const float4*>(&kS[d4 * 1024 + j * 4]);
#pragma unroll
                for (int qq = 0; qq < 4; qq++)
                    acc[qq][u] += qv[qq].x * kv.x + qv[qq].y * kv.y
                                + qv[qq].z * kv.z + qv[qq].w * kv.w;
            }
        }

#pragma unroll
        for (int qq = 0; qq < 4; qq++) {
            int wq = wq0 + qq, wq8 = wq >> 3;
            float sv[8], mx = -3.402823466e+38f;
#pragma unroll
            for (int u = 0; u < 8; u++) {
                int j = u * 32 + lane, hk = j >> 4, wk = j & 15;
                float xv = (acc[qq][u]
                            + grh[w * 128 + qq * 32 + hk - hq8 + 15]
                            + grw[w * 128 + qq * 32 + wk - wq8 + 15]) * 0.125f;
                sv[u] = xv;
                mx = fmaxf(mx, xv);
            }
#pragma unroll
            for (int o = 16; o > 0; o >>= 1)
                mx = fmaxf(mx, __shfl_xor_sync(0xffffffffu, mx, o));
            float sum = 0.f;
#pragma unroll
            for (int u = 0; u < 8; u++) { sv[u] = __expf(sv[u] - mx); sum += sv[u]; }
#pragma unroll
            for (int o = 16; o > 0; o >>= 1)
                sum += __shfl_xor_sync(0xffffffffu, sum, o);
            float inv = 1.f / sum;
#pragma unroll
            for (int u = 0; u < 8; u++) {
                float p = sv[u] * inv;
                attn_out[abase + (size_t)wq * 256 + u * 32 + lane] = p;
                pS[w * 1024 + qq * 256 + u * 32 + lane] = p;
            }
        }
        __syncwarp();

        float o0[4] = {0.f, 0.f, 0.f, 0.f}, o1[4] = {0.f, 0.f, 0.f, 0.f};
#pragma unroll 4
        for (int j = 0; j < 256; j++) {
            float v0 = vS[j * 64 + lane];
            float v1 = vS[j * 64 + lane + 32];
#pragma unroll
            for (int qq = 0; qq < 4; qq++) {
                float p = pS[w * 1024 + qq * 256 + j];
                o0[qq] += p * v0;
                o1[qq] += p * v1;
            }
        }
#pragma unroll
        for (int qq = 0; qq < 4; qq++) {
            oT[lane * 129 + wq0 + qq]        = o0[qq];
            oT[(lane + 32) * 129 + wq0 + qq] = o1[qq];
        }
        __syncwarp();
    }
    __syncthreads();
    for (int i = t; i < 64 * 128; i += 256) {
        int d = i >> 7, x = i & 127;
        g_y1[(((size_t)(b * CH + d * 4 + head)) * 128 + hq) * 128 + x] = oT[d * 129 + x];
    }
}

// ---------------------------------------------------------------------------
extern "C" void kernel_launch(void* const* d_in, const int* in_sizes, int n_in,
                              void* d_out, int out_size) {
    (void)in_sizes; (void)n_in; (void)out_size;
    const float* x    = (const float*)d_in[0];
    const float* dw1  = (const float*)d_in[1];
    const float* pw1  = (const float*)d_in[2];
    const float* relw = (const float*)d_in[3];
    const float* relh = (const float*)d_in[4];
    const float* dw2  = (const float*)d_in[5];
    const float* pw2  = (const float*)d_in[6];
    float* out  = (float*)d_out;
    float* attn = out + OUT_ELEMS;

    cudaFuncSetAttribute(attn_kernel, cudaFuncAttributeMaxDynamicSharedMemorySize,
                         ATTN_SMEM_FLOATS * 4);

    convert_w<<<1024, 256>>>(pw1, pw2);
    dw3x3_k1<<<OUT_ELEMS / 1024, 256>>>(x, dw1);
    tconv_y1<<<dim3(512, 8, 4), 256>>>();
    gemm_mma_pw1<<<dim3(512, 6), 256>>>();
    pool_kv<<<2048, 256>>>();
    transpose_q<<<4096, 256>>>();
    attn_kernel<<<dim3(128, HEADS, BATCH), 256, ATTN_SMEM_FLOATS * 4>>>(relw, relh, attn);
    dw3x3_k2<<<OUT_ELEMS / 1024, 256>>>(dw2);
    tconv_y3<<<dim3(512, 8, 4), 256>>>();
    gemm_mma_pw2<<<dim3(512, 2), 256>>>(out);
}

// round 9
// speedup vs baseline: 2.3551x; 1.8404x over previous
#include <cuda_runtime.h>
#include <cuda_bf16.h>
#include <cstdint>
#include <cstddef>

// ---------------------------------------------------------------------------
// SemRelAttention, HMMA everywhere:
//   convert_w / rel_build  : weights + rel tables -> bf16 hi/lo
//   dw3x3 -> tconv -> gemm_mma(pw1, K=768 split) -> qkv
//   pool_kv -> bf16 split K[key][d], V^T[d][key];  transpose_q -> bf16 Q hi/lo
//   attn: QK mma + rel mma + bias/softmax in regs + AV mma -> attn out + y2
//   dw3x3 -> tconv -> gemm_mma(pw2) -> out
// d_out = [ out : 4*256*128*128 | attn : 4*4*16384*256 ]  fp32
// ---------------------------------------------------------------------------

#define BATCH     4
#define CH        256
#define HW        16384
#define HEADS     4
#define DHEAD     64
#define NKEY      256
#define NT_TOTAL  65536
#define OUT_ELEMS (BATCH * CH * HW)

// ---------------- scratch (device globals) ----------------------------------
__device__ float g_y1[BATCH * CH * HW];                 // y1, then y2
__device__ float g_qkv[BATCH * 3 * CH * HW];            // qkv, head reused as y3
__device__ __align__(128) __nv_bfloat16 g_a1[768 * 768];   // [Ah|Al|Ah]
__device__ __align__(128) __nv_bfloat16 g_a2[256 * 768];
__device__ __align__(128) __nv_bfloat16 g_bT[(size_t)NT_TOTAL * 512]; // [Bh|Bl]
__device__ __align__(128) __nv_bfloat16 g_qTh[(size_t)BATCH * HEADS * HW * DHEAD];
__device__ __align__(128) __nv_bfloat16 g_qTl[(size_t)BATCH * HEADS * HW * DHEAD];
__device__ __align__(128) __nv_bfloat16 g_kTh[16 * NKEY * DHEAD];
__device__ __align__(128) __nv_bfloat16 g_kTl[16 * NKEY * DHEAD];
__device__ __align__(128) __nv_bfloat16 g_vTh[16 * DHEAD * NKEY];  // transposed [d][key]
__device__ __align__(128) __nv_bfloat16 g_vTl[16 * DHEAD * NKEY];
__device__ __align__(128) __nv_bfloat16 g_Rh[64 * 64];   // rows 0-30 relw, 32-62 relh
__device__ __align__(128) __nv_bfloat16 g_Rl[64 * 64];

// ======================= PTX helpers ========================================
__device__ __forceinline__ uint32_t smem_u32(const void* p) {
    uint32_t a;
    asm("{ .reg .u64 t; cvta.to.shared.u64 t, %1; cvt.u32.u64 %0, t; }" : "=r"(a) : "l"(p));
    return a;
}
__device__ __forceinline__ void cp16(uint32_t dst, const void* src) {
    asm volatile("{ .reg .u64 g; cvta.to.global.u64 g, %1; "
                 "cp.async.cg.shared.global [%0], [g], 16; }"
                 :: "r"(dst), "l"(src));
}
__device__ __forceinline__ void ldsm4(uint32_t* r, uint32_t a) {
    asm volatile("ldmatrix.sync.aligned.m8n8.x4.shared.b16 {%0,%1,%2,%3}, [%4];"
                 : "=r"(r[0]), "=r"(r[1]), "=r"(r[2]), "=r"(r[3]) : "r"(a));
}
__device__ __forceinline__ void mma16816(float* c, const uint32_t* a,
                                         uint32_t b0, uint32_t b1) {
    asm volatile("mma.sync.aligned.m16n8k16.row.col.f32.bf16.bf16.f32 "
                 "{%0,%1,%2,%3}, {%4,%5,%6,%7}, {%8,%9}, {%0,%1,%2,%3};"
                 : "+f"(c[0]), "+f"(c[1]), "+f"(c[2]), "+f"(c[3])
                 : "r"(a[0]), "r"(a[1]), "r"(a[2]), "r"(a[3]), "r"(b0), "r"(b1));
}
__device__ __forceinline__ uint32_t packbf(float a, float b) {
    __nv_bfloat162 h = __floats2bfloat162_rn(a, b);
    return *reinterpret_cast<uint32_t*>(&h);
}

// ---------------- weight split fp32 -> bf16 K-expanded ----------------------
__global__ __launch_bounds__(256) void convert_w(const float* __restrict__ pw1,
                                                 const float* __restrict__ pw2) {
    int idx = blockIdx.x * 256 + threadIdx.x;
    float f;
    if (idx < 768 * 256) f = pw1[idx]; else f = pw2[idx - 768 * 256];
    __nv_bfloat16 hi = __float2bfloat16_rn(f);
    __nv_bfloat16 lo = __float2bfloat16_rn(f - __bfloat162float(hi));
    if (idx < 768 * 256) {
        int m = idx >> 8, c = idx & 255;
        g_a1[m * 768 + c] = hi; g_a1[m * 768 + 256 + c] = lo; g_a1[m * 768 + 512 + c] = hi;
    } else {
        int r = idx - 768 * 256;
        int m = r >> 8, c = r & 255;
        g_a2[m * 768 + c] = hi; g_a2[m * 768 + 256 + c] = lo; g_a2[m * 768 + 512 + c] = hi;
    }
}

// ---------------- rel table build: [relw rows 0-30 | relh rows 32-62] -------
__global__ __launch_bounds__(256) void rel_build(const float* __restrict__ relw,
                                                 const float* __restrict__ relh) {
    int idx = blockIdx.x * 256 + threadIdx.x;   // 4096
    int row = idx >> 6, d = idx & 63;
    float v = 0.f;
    if (row < 31) v = relw[row * 64 + d];
    else if (row >= 32 && row < 63) v = relh[(row - 32) * 64 + d];
    __nv_bfloat16 hi = __float2bfloat16_rn(v);
    g_Rh[idx] = hi;
    g_Rl[idx] = __float2bfloat16_rn(v - __bfloat162float(hi));
}

// ---------------- transpose + split: [b][c][pos] f32 -> [n][512] bf16 -------
__device__ __forceinline__ void tconv_body(const float* __restrict__ in) {
    __shared__ float tile[32][33];
    int p0 = blockIdx.x * 32, c0 = blockIdx.y * 32, b = blockIdx.z;
    int t = threadIdx.x;
    {
        int ci = t >> 3, pj = (t & 7) * 4;
        float4 v = *reinterpret_cast<const float4*>(
            in + (((size_t)(b * 256 + c0 + ci)) << 14) + p0 + pj);
        tile[ci][pj] = v.x; tile[ci][pj + 1] = v.y;
        tile[ci][pj + 2] = v.z; tile[ci][pj + 3] = v.w;
    }
    __syncthreads();
    {
        int pi = t >> 3, cj = (t & 7) * 4;
        size_t n = (size_t)b * HW + p0 + pi;
        uint32_t hp[2], lp[2];
#pragma unroll
        for (int u = 0; u < 2; u++) {
            float f0 = tile[cj + 2 * u][pi], f1 = tile[cj + 2 * u + 1][pi];
            __nv_bfloat16 h0 = __float2bfloat16_rn(f0);
            __nv_bfloat16 h1 = __float2bfloat16_rn(f1);
            __nv_bfloat16 l0 = __float2bfloat16_rn(f0 - __bfloat162float(h0));
            __nv_bfloat16 l1 = __float2bfloat16_rn(f1 - __bfloat162float(h1));
            hp[u] = (uint32_t)__bfloat16_as_ushort(h0) | ((uint32_t)__bfloat16_as_ushort(h1) << 16);
            lp[u] = (uint32_t)__bfloat16_as_ushort(l0) | ((uint32_t)__bfloat16_as_ushort(l1) << 16);
        }
        *reinterpret_cast<uint2*>(&g_bT[n * 512 + c0 + cj]) = make_uint2(hp[0], hp[1]);
        *reinterpret_cast<uint2*>(&g_bT[n * 512 + 256 + c0 + cj]) = make_uint2(lp[0], lp[1]);
    }
}
__global__ __launch_bounds__(256) void tconv_y1() { tconv_body(g_y1); }
__global__ __launch_bounds__(256) void tconv_y3() { tconv_body(g_qkv); }

// ======================= HMMA GEMM, K=64 stages =============================
#define SROW 72
#define GBUF (128 * SROW * 2)         // 18432 B per buffer
#define GEMM_SMEM (4 * GBUF)          // A0 A1 B0 B1

__device__ __forceinline__ void gemm_mma_body(const __nv_bfloat16* __restrict__ A,
                                              float* __restrict__ C) {
    extern __shared__ char smg[];
    uint32_t sAb = smem_u32(smg);
    uint32_t sBb = sAb + 2 * GBUF;
    int t = threadIdx.x, lane = t & 31, w = t >> 5;
    int wm = w >> 1, wn = w & 1;
    int nt = blockIdx.x, mtb = blockIdx.y;
    int Mrows = gridDim.y * 128;

    const __nv_bfloat16* Ab = A + (size_t)mtb * 128 * 768;
    const __nv_bfloat16* Bb = g_bT + (size_t)nt * 128 * 512;

    float acc[2][8][4];
#pragma unroll
    for (int i = 0; i < 2; i++)
#pragma unroll
        for (int j = 0; j < 8; j++)
#pragma unroll
            for (int q = 0; q < 4; q++) acc[i][j][q] = 0.f;

    auto stage_load = [&](int s, int buf) {
        int ao = s * 64;
        int bo = (s < 4) ? s * 64 : ((s < 8) ? (s - 4) * 64 : (s - 8) * 64 + 256);
        uint32_t da = sAb + buf * GBUF;
        uint32_t db = sBb + buf * GBUF;
#pragma unroll
        for (int i = 0; i < 4; i++) {
            int idx = i * 256 + t;
            int row = idx >> 3, col = (idx & 7) * 8;
            cp16(da + (row * SROW + col) * 2, Ab + (size_t)row * 768 + ao + col);
            cp16(db + (row * SROW + col) * 2, Bb + (size_t)row * 512 + bo + col);
        }
        asm volatile("cp.async.commit_group;" ::: "memory");
    };

    stage_load(0, 0);
    for (int s = 0; s < 12; s++) {
        int buf = s & 1;
        if (s + 1 < 12) {
            stage_load(s + 1, buf ^ 1);
            asm volatile("cp.async.wait_group 1;" ::: "memory");
        } else {
            asm volatile("cp.async.wait_group 0;" ::: "memory");
        }
        __syncthreads();
        uint32_t aB = sAb + buf * GBUF;
        uint32_t bB = sBb + buf * GBUF;
#pragma unroll
        for (int k16 = 0; k16 < 4; k16++) {
            uint32_t af[2][4];
#pragma unroll
            for (int mt = 0; mt < 2; mt++) {
                int row = wm * 32 + mt * 16 + (lane & 15);
                int col = k16 * 16 + (lane >> 4) * 8;
                ldsm4(af[mt], aB + (row * SROW + col) * 2);
            }
#pragma unroll
            for (int nq = 0; nq < 4; nq++) {
                uint32_t bfr[4];
                int n = wn * 64 + nq * 16 + ((lane >> 4) << 3) + (lane & 7);
                int kc = k16 * 16 + ((lane >> 3) & 1) * 8;
                ldsm4(bfr, bB + (n * SROW + kc) * 2);
#pragma unroll
                for (int mt = 0; mt < 2; mt++) {
                    mma16816(acc[mt][nq * 2],     af[mt], bfr[0], bfr[1]);
                    mma16816(acc[mt][nq * 2 + 1], af[mt], bfr[2], bfr[3]);
                }
            }
        }
        __syncthreads();
    }

    int b = nt >> 7;
    int n0 = (nt & 127) * 128;
    size_t base = (size_t)b * Mrows * HW + (size_t)mtb * 128 * HW + n0;
#pragma unroll
    for (int mt = 0; mt < 2; mt++) {
        int row0 = wm * 32 + mt * 16 + (lane >> 2);
#pragma unroll
        for (int nq = 0; nq < 8; nq++) {
            int col = wn * 64 + nq * 8 + (lane & 3) * 2;
            *reinterpret_cast<float2*>(&C[base + (size_t)row0 * HW + col]) =
                make_float2(acc[mt][nq][0], acc[mt][nq][1]);
            *reinterpret_cast<float2*>(&C[base + (size_t)(row0 + 8) * HW + col]) =
                make_float2(acc[mt][nq][2], acc[mt][nq][3]);
        }
    }
}
__global__ __launch_bounds__(256) void gemm_mma_pw1() { gemm_mma_body(g_a1, g_qkv); }
__global__ __launch_bounds__(256) void gemm_mma_pw2(float* __restrict__ out) {
    gemm_mma_body(g_a2, out);
}

// ---------------- depthwise 3x3 ---------------------------------------------
__device__ __forceinline__ void dw3x3_body(const float* __restrict__ in,
                                           const float* __restrict__ wt,
                                           float* __restrict__ out) {
    int idx = blockIdx.x * 256 + threadIdx.x;
    int x4 = (idx & 31) << 2;
    int y  = (idx >> 5) & 127;
    int bc = idx >> 12;
    int c  = bc & 255;
    const float* wp = wt + c * 9;
    const float* ip = in + ((size_t)bc << 14);
    float4 acc = make_float4(0.f, 0.f, 0.f, 0.f);
#pragma unroll
    for (int dy = 0; dy < 3; dy++) {
        int yy = y + dy - 1;
        if (yy < 0 || yy > 127) continue;
        const float* rp = ip + (yy << 7);
        float4 cc = *reinterpret_cast<const float4*>(rp + x4);
        float lf = (x4 > 0)   ? rp[x4 - 1] : 0.f;
        float rt = (x4 < 124) ? rp[x4 + 4] : 0.f;
        float a = wp[dy * 3], b = wp[dy * 3 + 1], cw = wp[dy * 3 + 2];
        acc.x += a * lf   + b * cc.x + cw * cc.y;
        acc.y += a * cc.x + b * cc.y + cw * cc.z;
        acc.z += a * cc.y + b * cc.z + cw * cc.w;
        acc.w += a * cc.z + b * cc.w + cw * rt;
    }
    *reinterpret_cast<float4*>(out + ((size_t)idx << 2)) = acc;
}
__global__ __launch_bounds__(256) void dw3x3_k1(const float* __restrict__ x,
                                                const float* __restrict__ dw1) {
    dw3x3_body(x, dw1, g_y1);
}
__global__ __launch_bounds__(256) void dw3x3_k2(const float* __restrict__ dw2) {
    dw3x3_body(g_y1, dw2, g_qkv);
}

// ---------------- 8x8 max pool k,v -> bf16 split ----------------------------
__global__ __launch_bounds__(256) void pool_kv() {
    int idx = blockIdx.x * 256 + threadIdx.x;
    int wk = idx & 15;
    int hk = (idx >> 4) & 15;
    int c = (idx >> 8) & 255;
    int which = (idx >> 16) & 1;
    int b = idx >> 17;
    int ch = 256 + which * 256 + c;
    const float* src = g_qkv + (((size_t)(b * 768 + ch)) << 14) + ((hk * 8) << 7) + wk * 8;
    float m = -3.402823466e+38f;
#pragma unroll
    for (int dy = 0; dy < 8; dy++)
#pragma unroll
        for (int dx = 0; dx < 8; dx++)
            m = fmaxf(m, src[(dy << 7) + dx]);
    int head = c & 3, d = c >> 2;
    int bh = b * HEADS + head, key = hk * 16 + wk;
    __nv_bfloat16 hi = __float2bfloat16_rn(m);
    __nv_bfloat16 lo = __float2bfloat16_rn(m - __bfloat162float(hi));
    if (which == 0) {
        g_kTh[(bh * NKEY + key) * DHEAD + d] = hi;
        g_kTl[(bh * NKEY + key) * DHEAD + d] = lo;
    } else {
        g_vTh[(bh * DHEAD + d) * NKEY + key] = hi;
        g_vTl[(bh * DHEAD + d) * NKEY + key] = lo;
    }
}

// ---------------- q transpose -> bf16 split [b,head][p][d] ------------------
__global__ __launch_bounds__(256) void transpose_q() {
    __shared__ float tile[64 * 65];
    int bx = blockIdx.x;
    int p0 = (bx & 255) << 6;
    int head = (bx >> 8) & 3;
    int b = bx >> 10;
    int t = threadIdx.x;
#pragma unroll
    for (int i = 0; i < 16; i++) {
        int idx = i * 256 + t;
        int d = idx >> 6, p = idx & 63;
        tile[d * 65 + p] = g_qkv[(((size_t)(b * 768 + d * 4 + head)) << 14) + p0 + p];
    }
    __syncthreads();
    size_t base = (((size_t)(b * HEADS + head)) << 14) + p0;
#pragma unroll
    for (int i = 0; i < 16; i++) {
        int idx = i * 256 + t;
        int p = idx >> 6, d = idx & 63;
        float v = tile[d * 65 + p];
        __nv_bfloat16 hi = __float2bfloat16_rn(v);
        g_qTh[(base + p) * 64 + d] = hi;
        g_qTl[(base + p) * 64 + d] = __float2bfloat16_rn(v - __bfloat162float(hi));
    }
}

// ================= HMMA attention ===========================================
// grid (hq=128, head=4, b=4), 256 thr = 8 warps, warp tile 32(m) x 128(n).
#define AT_KH   0                    // 256 x 72 bf16
#define AT_KL   36864
#define AT_VH   0                    // overlay after QK: 64 x 264 bf16
#define AT_VL   33792
#define AT_QH   73728                // 128 x 72
#define AT_QL   92160
#define AT_RH   110592               // 64 x 72
#define AT_RL   119808
#define AT_LWH  129024               // float [128][66]; later vl stash / oT
#define AT_PM   162816               // float [128][2]
#define AT_PS   163840
#define AT_SMEM 164864

__global__ __launch_bounds__(256, 1) void attn_kernel(float* __restrict__ attn_out) {
    extern __shared__ char smc[];
    uint32_t sb = smem_u32(smc);
    int t = threadIdx.x, lane = t & 31, w = t >> 5;
    int wm = w >> 1, wn = w & 1;
    int hq = blockIdx.x, head = blockIdx.y, b = blockIdx.z;
    int bh = b * HEADS + head;
    int hq8 = hq >> 3;

    // ---- stage K, Q, R ----
    const __nv_bfloat16* kh = g_kTh + (size_t)bh * NKEY * DHEAD;
    const __nv_bfloat16* kl = g_kTl + (size_t)bh * NKEY * DHEAD;
    const __nv_bfloat16* qh = g_qTh + (((size_t)bh << 14) + (size_t)hq * 128) * 64;
    const __nv_bfloat16* ql = g_qTl + (((size_t)bh << 14) + (size_t)hq * 128) * 64;
#pragma unroll
    for (int i = 0; i < 8; i++) {
        int idx = i * 256 + t, row = idx >> 3, col = (idx & 7) * 8;
        cp16(sb + AT_KH + (row * 72 + col) * 2, kh + row * 64 + col);
        cp16(sb + AT_KL + (row * 72 + col) * 2, kl + row * 64 + col);
    }
#pragma unroll
    for (int i = 0; i < 4; i++) {
        int idx = i * 256 + t, row = idx >> 3, col = (idx & 7) * 8;
        cp16(sb + AT_QH + (row * 72 + col) * 2, qh + row * 64 + col);
        cp16(sb + AT_QL + (row * 72 + col) * 2, ql + row * 64 + col);
    }
#pragma unroll
    for (int i = 0; i < 2; i++) {
        int idx = i * 256 + t, row = idx >> 3, col = (idx & 7) * 8;
        cp16(sb + AT_RH + (row * 72 + col) * 2, g_Rh + row * 64 + col);
        cp16(sb + AT_RL + (row * 72 + col) * 2, g_Rl + row * 64 + col);
    }
    asm volatile("cp.async.commit_group;" ::: "memory");
    asm volatile("cp.async.wait_group 0;" ::: "memory");
    __syncthreads();

    uint32_t qsrc[3] = { sb + AT_QH, sb + AT_QL, sb + AT_QH };

    // ---- rel logits mma: wn=0 -> LW cols 0..31, wn=1 -> LH cols 32..63 ----
    {
        float rc[2][4][4];
#pragma unroll
        for (int i = 0; i < 2; i++)
#pragma unroll
            for (int j = 0; j < 4; j++)
#pragma unroll
                for (int q = 0; q < 4; q++) rc[i][j][q] = 0.f;
        uint32_t rsrc[3] = { sb + AT_RH, sb + AT_RH, sb + AT_RL };
#pragma unroll
        for (int term = 0; term < 3; term++)
#pragma unroll
            for (int k16 = 0; k16 < 4; k16++) {
                uint32_t af[2][4];
#pragma unroll
                for (int mt = 0; mt < 2; mt++) {
                    int row = wm * 32 + mt * 16 + (lane & 15);
                    int col = k16 * 16 + (lane >> 4) * 8;
                    ldsm4(af[mt], qsrc[term] + (row * 72 + col) * 2);
                }
#pragma unroll
                for (int nq = 0; nq < 2; nq++) {
                    uint32_t bfr[4];
                    int n = wn * 32 + nq * 16 + ((lane >> 4) << 3) + (lane & 7);
                    int kc = k16 * 16 + ((lane >> 3) & 1) * 8;
                    ldsm4(bfr, rsrc[term] + (n * 72 + kc) * 2);
#pragma unroll
                    for (int mt = 0; mt < 2; mt++) {
                        mma16816(rc[mt][nq * 2],     af[mt], bfr[0], bfr[1]);
                        mma16816(rc[mt][nq * 2 + 1], af[mt], bfr[2], bfr[3]);
                    }
                }
            }
        float* LWH = reinterpret_cast<float*>(smc + AT_LWH);
#pragma unroll
        for (int mt = 0; mt < 2; mt++) {
            int r0 = wm * 32 + mt * 16 + (lane >> 2);
#pragma unroll
            for (int nf = 0; nf < 4; nf++) {
                int c = wn * 32 + nf * 8 + (lane & 3) * 2;
                LWH[r0 * 66 + c]       = rc[mt][nf][0];
                LWH[r0 * 66 + c + 1]   = rc[mt][nf][1];
                LWH[(r0 + 8) * 66 + c]     = rc[mt][nf][2];
                LWH[(r0 + 8) * 66 + c + 1] = rc[mt][nf][3];
            }
        }
    }
    __syncthreads();

    // ---- QK mma: warp covers rows wm*32..+31, keys wn*128..+127 ----
    float acc[2][16][4];
#pragma unroll
    for (int i = 0; i < 2; i++)
#pragma unroll
        for (int j = 0; j < 16; j++)
#pragma unroll
            for (int q = 0; q < 4; q++) acc[i][j][q] = 0.f;
    {
        uint32_t ksrc[3] = { sb + AT_KH, sb + AT_KH, sb + AT_KL };
#pragma unroll
        for (int term = 0; term < 3; term++)
#pragma unroll
            for (int k16 = 0; k16 < 4; k16++) {
                uint32_t af[2][4];
#pragma unroll
                for (int mt = 0; mt < 2; mt++) {
                    int row = wm * 32 + mt * 16 + (lane & 15);
                    int col = k16 * 16 + (lane >> 4) * 8;
                    ldsm4(af[mt], qsrc[term] + (row * 72 + col) * 2);
                }
#pragma unroll
                for (int nq = 0; nq < 8; nq++) {
                    uint32_t bfr[4];
                    int n = wn * 128 + nq * 16 + ((lane >> 4) << 3) + (lane & 7);
                    int kc = k16 * 16 + ((lane >> 3) & 1) * 8;
                    ldsm4(bfr, ksrc[term] + (n * 72 + kc) * 2);
#pragma unroll
                    for (int mt = 0; mt < 2; mt++) {
                        mma16816(acc[mt][nq * 2],     af[mt], bfr[0], bfr[1]);
                        mma16816(acc[mt][nq * 2 + 1], af[mt], bfr[2], bfr[3]);
                    }
                }
            }
    }
    __syncthreads();   // K reads complete -> safe to overlay V

    // ---- launch V loads (overlap with softmax) ----
    {
        const __nv_bfloat16* vh = g_vTh + (size_t)bh * DHEAD * NKEY;
        const __nv_bfloat16* vl = g_vTl + (size_t)bh * DHEAD * NKEY;
#pragma unroll
        for (int i = 0; i < 8; i++) {
            int idx = i * 256 + t, row = idx >> 5, col = (idx & 31) * 8;
            cp16(sb + AT_VH + (row * 264 + col) * 2, vh + row * 256 + col);
            cp16(sb + AT_VL + (row * 264 + col) * 2, vl + row * 256 + col);
        }
        asm volatile("cp.async.commit_group;" ::: "memory");
    }

    // ---- bias + softmax ----
    float* LWH = reinterpret_cast<float*>(smc + AT_LWH);
    float* pm = reinterpret_cast<float*>(smc + AT_PM);
    float* ps = reinterpret_cast<float*>(smc + AT_PS);
    int r0t[2], r1t[2];
    float mx[2][2];
#pragma unroll
    for (int mt = 0; mt < 2; mt++) {
        r0t[mt] = wm * 32 + mt * 16 + (lane >> 2);
        r1t[mt] = r0t[mt] + 8;
        mx[mt][0] = -3.402823466e+38f; mx[mt][1] = -3.402823466e+38f;
        int wq80 = r0t[mt] >> 3, wq81 = r1t[mt] >> 3;
        const float* L0 = &LWH[r0t[mt] * 66];
        const float* L1 = &LWH[r1t[mt] * 66];
#pragma unroll
        for (int nf = 0; nf < 16; nf++) {
            int j = wn * 16 + nf;
            int hk = j >> 1;
            int c0 = (j & 1) * 8 + (lane & 3) * 2;
            float bh0 = L0[32 + hk - hq8 + 15];
            float bh1 = L1[32 + hk - hq8 + 15];
            float v0 = (acc[mt][nf][0] + bh0 + L0[c0 - wq80 + 15])     * 0.125f;
            float v1 = (acc[mt][nf][1] + bh0 + L0[c0 + 1 - wq80 + 15]) * 0.125f;
            float v2 = (acc[mt][nf][2] + bh1 + L1[c0 - wq81 + 15])     * 0.125f;
            float v3 = (acc[mt][nf][3] + bh1 + L1[c0 + 1 - wq81 + 15]) * 0.125f;
            acc[mt][nf][0] = v0; acc[mt][nf][1] = v1;
            acc[mt][nf][2] = v2; acc[mt][nf][3] = v3;
            mx[mt][0] = fmaxf(mx[mt][0], fmaxf(v0, v1));
            mx[mt][1] = fmaxf(mx[mt][1], fmaxf(v2, v3));
        }
#pragma unroll
        for (int o = 1; o <= 2; o <<= 1) {
            mx[mt][0] = fmaxf(mx[mt][0], __shfl_xor_sync(0xffffffffu, mx[mt][0], o));
            mx[mt][1] = fmaxf(mx[mt][1], __shfl_xor_sync(0xffffffffu, mx[mt][1], o));
        }
        pm[r0t[mt] * 2 + wn] = mx[mt][0];
        pm[r1t[mt] * 2 + wn] = mx[mt][1];
    }
    __syncthreads();
    float sum[2][2];
#pragma unroll
    for (int mt = 0; mt < 2; mt++) {
        float M0 = fmaxf(pm[r0t[mt] * 2], pm[r0t[mt] * 2 + 1]);
        float M1 = fmaxf(pm[r1t[mt] * 2], pm[r1t[mt] * 2 + 1]);
        sum[mt][0] = 0.f; sum[mt][1] = 0.f;
#pragma unroll
        for (int nf = 0; nf < 16; nf++) {
            float e0 = __expf(acc[mt][nf][0] - M0);
            float e1 = __expf(acc[mt][nf][1] - M0);
            float e2 = __expf(acc[mt][nf][2] - M1);
            float e3 = __expf(acc[mt][nf][3] - M1);
            acc[mt][nf][0] = e0; acc[mt][nf][1] = e1;
            acc[mt][nf][2] = e2; acc[mt][nf][3] = e3;
            sum[mt][0] += e0 + e1; sum[mt][1] += e2 + e3;
        }
#pragma unroll
        for (int o = 1; o <= 2; o <<= 1) {
            sum[mt][0] += __shfl_xor_sync(0xffffffffu, sum[mt][0], o);
            sum[mt][1] += __shfl_xor_sync(0xffffffffu, sum[mt][1], o);
        }
        ps[r0t[mt] * 2 + wn] = sum[mt][0];
        ps[r1t[mt] * 2 + wn] = sum[mt][1];
    }
    __syncthreads();

    // ---- normalize, write attn, pack P frags (hi regs + lo stash) ----
    size_t abase = ((size_t)bh * HW + (size_t)hq * 128) * NKEY;
    uint32_t uh[2][16], vh_[2][16], ul[2][16];
    uint32_t* vlS = reinterpret_cast<uint32_t*>(smc + AT_LWH) + t * 32;
#pragma unroll
    for (int mt = 0; mt < 2; mt++) {
        float inv0 = 1.f / (ps[r0t[mt] * 2] + ps[r0t[mt] * 2 + 1]);
        float inv1 = 1.f / (ps[r1t[mt] * 2] + ps[r1t[mt] * 2 + 1]);
#pragma unroll
        for (int nf = 0; nf < 16; nf++) {
            int j = wn * 16 + nf;
            int col = j * 8 + (lane & 3) * 2;
            float p0 = acc[mt][nf][0] * inv0, p1 = acc[mt][nf][1] * inv0;
            float p2 = acc[mt][nf][2] * inv1, p3 = acc[mt][nf][3] * inv1;
            *reinterpret_cast<float2*>(&attn_out[abase + (size_t)r0t[mt] * 256 + col]) =
                make_float2(p0, p1);
            *reinterpret_cast<float2*>(&attn_out[abase + (size_t)r1t[mt] * 256 + col]) =
                make_float2(p2, p3);
            uint32_t h01 = packbf(p0, p1), h23 = packbf(p2, p3);
            uh[mt][nf] = h01; vh_[mt][nf] = h23;
            __nv_bfloat162 hh01 = *reinterpret_cast<__nv_bfloat162*>(&h01);
            __nv_bfloat162 hh23 = *reinterpret_cast<__nv_bfloat162*>(&h23);
            ul[mt][nf] = packbf(p0 - __bfloat162float(hh01.x), p1 - __bfloat162float(hh01.y));
            vlS[mt * 16 + nf] = packbf(p2 - __bfloat162float(hh23.x), p3 - __bfloat162float(hh23.y));
        }
    }

    // ---- AV mma ----
    asm volatile("cp.async.wait_group 0;" ::: "memory");
    __syncthreads();
    float oacc[2][8][4];
#pragma unroll
    for (int i = 0; i < 2; i++)
#pragma unroll
        for (int j = 0; j < 8; j++)
#pragma unroll
            for (int q = 0; q < 4; q++) oacc[i][j][q] = 0.f;
#pragma unroll
    for (int kk = 0; kk < 8; kk++) {
        uint32_t afh[2][4], afl[2][4];
#pragma unroll
        for (int mt = 0; mt < 2; mt++) {
            afh[mt][0] = uh[mt][2 * kk];     afh[mt][1] = vh_[mt][2 * kk];
            afh[mt][2] = uh[mt][2 * kk + 1]; afh[mt][3] = vh_[mt][2 * kk + 1];
            afl[mt][0] = ul[mt][2 * kk];     afl[mt][1] = vlS[mt * 16 + 2 * kk];
            afl[mt][2] = ul[mt][2 * kk + 1]; afl[mt][3] = vlS[mt * 16 + 2 * kk + 1];
        }
        int kc = wn * 128 + kk * 16 + ((lane >> 3) & 1) * 8;
#pragma unroll
        for (int nq = 0; nq < 4; nq++) {
            int n = nq * 16 + ((lane >> 4) << 3) + (lane & 7);
            uint32_t bh_[4], bl_[4];
            ldsm4(bh_, sb + AT_VH + (n * 264 + kc) * 2);
            ldsm4(bl_, sb + AT_VL + (n * 264 + kc) * 2);
#pragma unroll
            for (int mt = 0; mt < 2; mt++) {
                mma16816(oacc[mt][nq * 2],     afh[mt], bh_[0], bh_[1]);
                mma16816(oacc[mt][nq * 2 + 1], afh[mt], bh_[2], bh_[3]);
                mma16816(oacc[mt][nq * 2],     afl[mt], bh_[0], bh_[1]);
                mma16816(oacc[mt][nq * 2 + 1], afl[mt], bh_[2], bh_[3]);
                mma16816(oacc[mt][nq * 2],     afh[mt], bl_[0], bl_[1]);
                mma16816(oacc[mt][nq * 2 + 1], afh[mt], bl_[2], bl_[3]);
            }
        }
    }

    // ---- cross-warp (wn) reduce into oT, then write y2 ----
    float* oT = reinterpret_cast<float*>(smc + AT_LWH);   // [64][129]
    __syncthreads();      // vlS reads done
    if (wn == 0) {
#pragma unroll
        for (int mt = 0; mt < 2; mt++)
#pragma unroll
            for (int nf = 0; nf < 8; nf++) {
                int d = nf * 8 + (lane & 3) * 2;
                oT[d * 129 + r0t[mt]]       = oacc[mt][nf][0];
                oT[(d + 1) * 129 + r0t[mt]] = oacc[mt][nf][1];
                oT[d * 129 + r1t[mt]]       = oacc[mt][nf][2];
                oT[(d + 1) * 129 + r1t[mt]] = oacc[mt][nf][3];
            }
    }
    __syncthreads();
    if (wn == 1) {
#pragma unroll
        for (int mt = 0; mt < 2; mt++)
#pragma unroll
            for (int nf = 0; nf < 8; nf++) {
                int d = nf * 8 + (lane & 3) * 2;
                oT[d * 129 + r0t[mt]]       += oacc[mt][nf][0];
                oT[(d + 1) * 129 + r0t[mt]] += oacc[mt][nf][1];
                oT[d * 129 + r1t[mt]]       += oacc[mt][nf][2];
                oT[(d + 1) * 129 + r1t[mt]] += oacc[mt][nf][3];
            }
    }
    __syncthreads();
    for (int i = t; i < 64 * 128; i += 256) {
        int d = i >> 7, x = i & 127;
        g_y1[(((size_t)(b * CH + d * 4 + head)) * 128 + hq) * 128 + x] = oT[d * 129 + x];
    }
}

// ---------------------------------------------------------------------------
extern "C" void kernel_launch(void* const* d_in, const int* in_sizes, int n_in,
                              void* d_out, int out_size) {
    (void)in_sizes; (void)n_in; (void)out_size;
    const float* x    = (const float*)d_in[0];
    const float* dw1  = (const float*)d_in[1];
    const float* pw1  = (const float*)d_in[2];
    const float* relw = (const float*)d_in[3];
    const float* relh = (const float*)d_in[4];
    const float* dw2  = (const float*)d_in[5];
    const float* pw2  = (const float*)d_in[6];
    float* out  = (float*)d_out;
    float* attn = out + OUT_ELEMS;

    cudaFuncSetAttribute(attn_kernel, cudaFuncAttributeMaxDynamicSharedMemorySize, AT_SMEM);
    cudaFuncSetAttribute(gemm_mma_pw1, cudaFuncAttributeMaxDynamicSharedMemorySize, GEMM_SMEM);
    cudaFuncSetAttribute(gemm_mma_pw2, cudaFuncAttributeMaxDynamicSharedMemorySize, GEMM_SMEM);

    convert_w<<<1024, 256>>>(pw1, pw2);
    rel_build<<<16, 256>>>(relw, relh);
    dw3x3_k1<<<OUT_ELEMS / 1024, 256>>>(x, dw1);
    tconv_y1<<<dim3(512, 8, 4), 256>>>();
    gemm_mma_pw1<<<dim3(512, 6), 256, GEMM_SMEM>>>();
    pool_kv<<<2048, 256>>>();
    transpose_q<<<4096, 256>>>();
    attn_kernel<<<dim3(128, HEADS, BATCH), 256, AT_SMEM>>>(attn);
    dw3x3_k2<<<OUT_ELEMS / 1024, 256>>>(dw2);
    tconv_y3<<<dim3(512, 8, 4), 256>>>();
    gemm_mma_pw2<<<dim3(512, 2), 256, GEMM_SMEM>>>(out);
}

// round 10
// speedup vs baseline: 2.3761x; 1.0089x over previous
#include <cuda_runtime.h>
#include <cuda_bf16.h>
#include <cstdint>
#include <cstddef>

// ---------------------------------------------------------------------------
// SemRelAttention, HMMA everywhere:
//   convert_w / rel_build : weights + rel tables -> bf16 hi/lo
//   dwt(x,dw1)            : fused dw3x3 + bf16 split + transpose -> g_bT
//   gemm_mma pw1 (K=768 split, 3-stage cp.async) -> g_qkv
//   pool_kv / transpose_q : bf16 split K,V,Q
//   attn (QK mma + rel mma + softmax + AV mma) -> attn region + y2 (=g_y1)
//   dwt(y2,dw2) -> g_bT ; gemm_mma pw2 -> out region
// d_out = [ out : 4*256*128*128 | attn : 4*4*16384*256 ]  fp32
// ---------------------------------------------------------------------------

#define BATCH     4
#define CH        256
#define HW        16384
#define HEADS     4
#define DHEAD     64
#define NKEY      256
#define NT_TOTAL  65536
#define OUT_ELEMS (BATCH * CH * HW)

// ---------------- scratch (device globals) ----------------------------------
__device__ float g_y1[BATCH * CH * HW];                 // y2 (attn output, ch layout)
__device__ float g_qkv[BATCH * 3 * CH * HW];
__device__ __align__(128) __nv_bfloat16 g_a1[768 * 768];   // [Ah|Al|Ah]
__device__ __align__(128) __nv_bfloat16 g_a2[256 * 768];
__device__ __align__(128) __nv_bfloat16 g_bT[(size_t)NT_TOTAL * 512]; // [Bh|Bl]
__device__ __align__(128) __nv_bfloat16 g_qTh[(size_t)BATCH * HEADS * HW * DHEAD];
__device__ __align__(128) __nv_bfloat16 g_qTl[(size_t)BATCH * HEADS * HW * DHEAD];
__device__ __align__(128) __nv_bfloat16 g_kTh[16 * NKEY * DHEAD];
__device__ __align__(128) __nv_bfloat16 g_kTl[16 * NKEY * DHEAD];
__device__ __align__(128) __nv_bfloat16 g_vTh[16 * DHEAD * NKEY];  // [d][key]
__device__ __align__(128) __nv_bfloat16 g_vTl[16 * DHEAD * NKEY];
__device__ __align__(128) __nv_bfloat16 g_Rh[64 * 64];   // rows 0-30 relw, 32-62 relh
__device__ __align__(128) __nv_bfloat16 g_Rl[64 * 64];

// ======================= PTX helpers ========================================
__device__ __forceinline__ uint32_t smem_u32(const void* p) {
    uint32_t a;
    asm("{ .reg .u64 t; cvta.to.shared.u64 t, %1; cvt.u32.u64 %0, t; }" : "=r"(a) : "l"(p));
    return a;
}
__device__ __forceinline__ void cp16(uint32_t dst, const void* src) {
    asm volatile("{ .reg .u64 g; cvta.to.global.u64 g, %1; "
                 "cp.async.cg.shared.global [%0], [g], 16; }"
                 :: "r"(dst), "l"(src));
}
__device__ __forceinline__ void ldsm4(uint32_t* r, uint32_t a) {
    asm volatile("ldmatrix.sync.aligned.m8n8.x4.shared.b16 {%0,%1,%2,%3}, [%4];"
                 : "=r"(r[0]), "=r"(r[1]), "=r"(r[2]), "=r"(r[3]) : "r"(a));
}
__device__ __forceinline__ void mma16816(float* c, const uint32_t* a,
                                         uint32_t b0, uint32_t b1) {
    asm volatile("mma.sync.aligned.m16n8k16.row.col.f32.bf16.bf16.f32 "
                 "{%0,%1,%2,%3}, {%4,%5,%6,%7}, {%8,%9}, {%0,%1,%2,%3};"
                 : "+f"(c[0]), "+f"(c[1]), "+f"(c[2]), "+f"(c[3])
                 : "r"(a[0]), "r"(a[1]), "r"(a[2]), "r"(a[3]), "r"(b0), "r"(b1));
}
__device__ __forceinline__ uint32_t packbf(float a, float b) {
    __nv_bfloat162 h = __floats2bfloat162_rn(a, b);
    return *reinterpret_cast<uint32_t*>(&h);
}

// ---------------- weight split fp32 -> bf16 K-expanded ----------------------
__global__ __launch_bounds__(256) void convert_w(const float* __restrict__ pw1,
                                                 const float* __restrict__ pw2) {
    int idx = blockIdx.x * 256 + threadIdx.x;
    float f;
    if (idx < 768 * 256) f = pw1[idx]; else f = pw2[idx - 768 * 256];
    __nv_bfloat16 hi = __float2bfloat16_rn(f);
    __nv_bfloat16 lo = __float2bfloat16_rn(f - __bfloat162float(hi));
    if (idx < 768 * 256) {
        int m = idx >> 8, c = idx & 255;
        g_a1[m * 768 + c] = hi; g_a1[m * 768 + 256 + c] = lo; g_a1[m * 768 + 512 + c] = hi;
    } else {
        int r = idx - 768 * 256;
        int m = r >> 8, c = r & 255;
        g_a2[m * 768 + c] = hi; g_a2[m * 768 + 256 + c] = lo; g_a2[m * 768 + 512 + c] = hi;
    }
}

// ---------------- rel table build -------------------------------------------
__global__ __launch_bounds__(256) void rel_build(const float* __restrict__ relw,
                                                 const float* __restrict__ relh) {
    int idx = blockIdx.x * 256 + threadIdx.x;   // 4096
    int row = idx >> 6, d = idx & 63;
    float v = 0.f;
    if (row < 31) v = relw[row * 64 + d];
    else if (row >= 32 && row < 63) v = relh[(row - 32) * 64 + d];
    __nv_bfloat16 hi = __float2bfloat16_rn(v);
    g_Rh[idx] = hi;
    g_Rl[idx] = __float2bfloat16_rn(v - __bfloat162float(hi));
}

// ========== fused depthwise 3x3 + bf16 hi/lo split + transpose ==============
// grid (16 ystrips, 16 ctiles, 4 b), 256 thr; strip = 8 rows x 128 cols x 16 ch.
// sIn [16ch][10 rows][136]: data cols 4..131, halo zeros at 3 and 132.
#define DWT_SMEM (16 * 10 * 136 * 4)     // 87040

__global__ __launch_bounds__(256) void dwt(const float* __restrict__ in,
                                           const float* __restrict__ wt,
                                           int ldc0) {   // base channel offset in wt/in
    extern __shared__ float sIn[];
    __shared__ float sW[144];
    int t = threadIdx.x;
    int tc = t >> 4, l = t & 15;
    int y0 = blockIdx.x * 8, c0 = blockIdx.y * 16, b = blockIdx.z;

    const float* ip = in + (((size_t)(b * 256 + c0 + tc)) << 14);
#pragma unroll
    for (int r = 0; r < 10; r++) {
        int yy = y0 - 1 + r;
        float4 v0 = make_float4(0.f, 0.f, 0.f, 0.f), v1 = v0;
        if (yy >= 0 && yy < 128) {
            v0 = *reinterpret_cast<const float4*>(ip + (yy << 7) + l * 8);
            v1 = *reinterpret_cast<const float4*>(ip + (yy << 7) + l * 8 + 4);
        }
        float* dst = sIn + (tc * 10 + r) * 136 + 4 + l * 8;
        *reinterpret_cast<float4*>(dst) = v0;
        *reinterpret_cast<float4*>(dst + 4) = v1;
    }
    if (l < 10) {
        sIn[(tc * 10 + l) * 136 + 3] = 0.f;
        sIn[(tc * 10 + l) * 136 + 132] = 0.f;
    }
    if (t < 144) sW[t] = wt[(size_t)(c0 + ldc0) * 9 + t];
    __syncthreads();

    size_t nbase = (size_t)b * HW + (size_t)y0 * 128;
#pragma unroll
    for (int i = 0; i < 4; i++) {
        int p = i * 256 + t;
        int x = p & 127, y = p >> 7;
        float o[16];
#pragma unroll
        for (int c = 0; c < 16; c++) {
            const float* base = sIn + (c * 10 + y) * 136 + 3 + x;
            const float* w = sW + c * 9;
            float s = 0.f;
#pragma unroll
            for (int dy = 0; dy < 3; dy++) {
                const float* rp = base + dy * 136;
                s += rp[0] * w[dy * 3] + rp[1] * w[dy * 3 + 1] + rp[2] * w[dy * 3 + 2];
            }
            o[c] = s;
        }
        uint32_t hp[8], lp[8];
#pragma unroll
        for (int q = 0; q < 8; q++) {
            __nv_bfloat16 h0 = __float2bfloat16_rn(o[2 * q]);
            __nv_bfloat16 h1 = __float2bfloat16_rn(o[2 * q + 1]);
            hp[q] = (uint32_t)__bfloat16_as_ushort(h0) |
                    ((uint32_t)__bfloat16_as_ushort(h1) << 16);
            lp[q] = packbf(o[2 * q] - __bfloat162float(h0),
                           o[2 * q + 1] - __bfloat162float(h1));
        }
        __nv_bfloat16* gp = g_bT + (nbase + p) * 512 + c0;
        *reinterpret_cast<uint4*>(gp)           = make_uint4(hp[0], hp[1], hp[2], hp[3]);
        *reinterpret_cast<uint4*>(gp + 8)       = make_uint4(hp[4], hp[5], hp[6], hp[7]);
        *reinterpret_cast<uint4*>(gp + 256)     = make_uint4(lp[0], lp[1], lp[2], lp[3]);
        *reinterpret_cast<uint4*>(gp + 256 + 8) = make_uint4(lp[4], lp[5], lp[6], lp[7]);
    }
}

// ======================= HMMA GEMM, K=64 stages, 3-buffer ===================
#define SROW 72
#define GBUF (128 * SROW * 2)            // 18432 B
#define GEMM_SMEM (6 * GBUF)             // A0-2, B0-2 = 110592

__device__ __forceinline__ void gemm_mma_body(const __nv_bfloat16* __restrict__ A,
                                              float* __restrict__ C) {
    extern __shared__ char smg[];
    uint32_t sAb = smem_u32(smg);
    uint32_t sBb = sAb + 3 * GBUF;
    int t = threadIdx.x, lane = t & 31, w = t >> 5;
    int wm = w >> 1, wn = w & 1;
    int nt = blockIdx.x, mtb = blockIdx.y;
    int Mrows = gridDim.y * 128;

    const __nv_bfloat16* Ab = A + (size_t)mtb * 128 * 768;
    const __nv_bfloat16* Bb = g_bT + (size_t)nt * 128 * 512;

    float acc[2][8][4];
#pragma unroll
    for (int i = 0; i < 2; i++)
#pragma unroll
        for (int j = 0; j < 8; j++)
#pragma unroll
            for (int q = 0; q < 4; q++) acc[i][j][q] = 0.f;

    auto stage_load = [&](int s, int buf) {
        int ao = s * 64;
        int bo = (s < 4) ? s * 64 : ((s < 8) ? (s - 4) * 64 : (s - 8) * 64 + 256);
        uint32_t da = sAb + buf * GBUF;
        uint32_t db = sBb + buf * GBUF;
#pragma unroll
        for (int i = 0; i < 4; i++) {
            int idx = i * 256 + t;
            int row = idx >> 3, col = (idx & 7) * 8;
            cp16(da + (row * SROW + col) * 2, Ab + (size_t)row * 768 + ao + col);
            cp16(db + (row * SROW + col) * 2, Bb + (size_t)row * 512 + bo + col);
        }
        asm volatile("cp.async.commit_group;" ::: "memory");
    };

    stage_load(0, 0);
    stage_load(1, 1);
    for (int s = 0; s < 12; s++) {
        int buf = s % 3;
        asm volatile("cp.async.wait_group 1;" ::: "memory");
        __syncthreads();
        if (s + 2 < 12) stage_load(s + 2, (s + 2) % 3);
        uint32_t aB = sAb + buf * GBUF;
        uint32_t bB = sBb + buf * GBUF;
#pragma unroll
        for (int k16 = 0; k16 < 4; k16++) {
            uint32_t af[2][4];
#pragma unroll
            for (int mt = 0; mt < 2; mt++) {
                int row = wm * 32 + mt * 16 + (lane & 15);
                int col = k16 * 16 + (lane >> 4) * 8;
                ldsm4(af[mt], aB + (row * SROW + col) * 2);
            }
#pragma unroll
            for (int nq = 0; nq < 4; nq++) {
                uint32_t bfr[4];
                int n = wn * 64 + nq * 16 + ((lane >> 4) << 3) + (lane & 7);
                int kc = k16 * 16 + ((lane >> 3) & 1) * 8;
                ldsm4(bfr, bB + (n * SROW + kc) * 2);
#pragma unroll
                for (int mt = 0; mt < 2; mt++) {
                    mma16816(acc[mt][nq * 2],     af[mt], bfr[0], bfr[1]);
                    mma16816(acc[mt][nq * 2 + 1], af[mt], bfr[2], bfr[3]);
                }
            }
        }
    }

    int b = nt >> 7;
    int n0 = (nt & 127) * 128;
    size_t base = (size_t)b * Mrows * HW + (size_t)mtb * 128 * HW + n0;
#pragma unroll
    for (int mt = 0; mt < 2; mt++) {
        int row0 = wm * 32 + mt * 16 + (lane >> 2);
#pragma unroll
        for (int nq = 0; nq < 8; nq++) {
            int col = wn * 64 + nq * 8 + (lane & 3) * 2;
            *reinterpret_cast<float2*>(&C[base + (size_t)row0 * HW + col]) =
                make_float2(acc[mt][nq][0], acc[mt][nq][1]);
            *reinterpret_cast<float2*>(&C[base + (size_t)(row0 + 8) * HW + col]) =
                make_float2(acc[mt][nq][2], acc[mt][nq][3]);
        }
    }
}
__global__ __launch_bounds__(256) void gemm_mma_pw1() { gemm_mma_body(g_a1, g_qkv); }
__global__ __launch_bounds__(256) void gemm_mma_pw2(float* __restrict__ out) {
    gemm_mma_body(g_a2, out);
}

// ---------------- 8x8 max pool k,v -> bf16 split ----------------------------
__global__ __launch_bounds__(256) void pool_kv() {
    int idx = blockIdx.x * 256 + threadIdx.x;
    int wk = idx & 15;
    int hk = (idx >> 4) & 15;
    int c = (idx >> 8) & 255;
    int which = (idx >> 16) & 1;
    int b = idx >> 17;
    int ch = 256 + which * 256 + c;
    const float* src = g_qkv + (((size_t)(b * 768 + ch)) << 14) + ((hk * 8) << 7) + wk * 8;
    float m = -3.402823466e+38f;
#pragma unroll
    for (int dy = 0; dy < 8; dy++)
#pragma unroll
        for (int dx = 0; dx < 8; dx++)
            m = fmaxf(m, src[(dy << 7) + dx]);
    int head = c & 3, d = c >> 2;
    int bh = b * HEADS + head, key = hk * 16 + wk;
    __nv_bfloat16 hi = __float2bfloat16_rn(m);
    __nv_bfloat16 lo = __float2bfloat16_rn(m - __bfloat162float(hi));
    if (which == 0) {
        g_kTh[(bh * NKEY + key) * DHEAD + d] = hi;
        g_kTl[(bh * NKEY + key) * DHEAD + d] = lo;
    } else {
        g_vTh[(bh * DHEAD + d) * NKEY + key] = hi;
        g_vTl[(bh * DHEAD + d) * NKEY + key] = lo;
    }
}

// ---------------- q transpose -> bf16 split [b,head][p][d] ------------------
__global__ __launch_bounds__(256) void transpose_q() {
    __shared__ float tile[64 * 65];
    int bx = blockIdx.x;
    int p0 = (bx & 255) << 6;
    int head = (bx >> 8) & 3;
    int b = bx >> 10;
    int t = threadIdx.x;
#pragma unroll
    for (int i = 0; i < 16; i++) {
        int idx = i * 256 + t;
        int d = idx >> 6, p = idx & 63;
        tile[d * 65 + p] = g_qkv[(((size_t)(b * 768 + d * 4 + head)) << 14) + p0 + p];
    }
    __syncthreads();
    size_t base = (((size_t)(b * HEADS + head)) << 14) + p0;
#pragma unroll
    for (int i = 0; i < 16; i++) {
        int idx = i * 256 + t;
        int p = idx >> 6, d = idx & 63;
        float v = tile[d * 65 + p];
        __nv_bfloat16 hi = __float2bfloat16_rn(v);
        g_qTh[(base + p) * 64 + d] = hi;
        g_qTl[(base + p) * 64 + d] = __float2bfloat16_rn(v - __bfloat162float(hi));
    }
}

// ================= HMMA attention ===========================================
#define AT_KH   0
#define AT_KL   36864
#define AT_VH   0
#define AT_VL   33792
#define AT_QH   73728
#define AT_QL   92160
#define AT_RH   110592
#define AT_RL   119808
#define AT_LWH  129024
#define AT_PM   162816
#define AT_PS   163840
#define AT_SMEM 164864

__global__ __launch_bounds__(256, 1) void attn_kernel(float* __restrict__ attn_out) {
    extern __shared__ char smc[];
    uint32_t sb = smem_u32(smc);
    int t = threadIdx.x, lane = t & 31, w = t >> 5;
    int wm = w >> 1, wn = w & 1;
    int hq = blockIdx.x, head = blockIdx.y, b = blockIdx.z;
    int bh = b * HEADS + head;
    int hq8 = hq >> 3;

    const __nv_bfloat16* kh = g_kTh + (size_t)bh * NKEY * DHEAD;
    const __nv_bfloat16* kl = g_kTl + (size_t)bh * NKEY * DHEAD;
    const __nv_bfloat16* qh = g_qTh + (((size_t)bh << 14) + (size_t)hq * 128) * 64;
    const __nv_bfloat16* ql = g_qTl + (((size_t)bh << 14) + (size_t)hq * 128) * 64;
#pragma unroll
    for (int i = 0; i < 8; i++) {
        int idx = i * 256 + t, row = idx >> 3, col = (idx & 7) * 8;
        cp16(sb + AT_KH + (row * 72 + col) * 2, kh + row * 64 + col);
        cp16(sb + AT_KL + (row * 72 + col) * 2, kl + row * 64 + col);
    }
#pragma unroll
    for (int i = 0; i < 4; i++) {
        int idx = i * 256 + t, row = idx >> 3, col = (idx & 7) * 8;
        cp16(sb + AT_QH + (row * 72 + col) * 2, qh + row * 64 + col);
        cp16(sb + AT_QL + (row * 72 + col) * 2, ql + row * 64 + col);
    }
#pragma unroll
    for (int i = 0; i < 2; i++) {
        int idx = i * 256 + t, row = idx >> 3, col = (idx & 7) * 8;
        cp16(sb + AT_RH + (row * 72 + col) * 2, g_Rh + row * 64 + col);
        cp16(sb + AT_RL + (row * 72 + col) * 2, g_Rl + row * 64 + col);
    }
    asm volatile("cp.async.commit_group;" ::: "memory");
    asm volatile("cp.async.wait_group 0;" ::: "memory");
    __syncthreads();

    uint32_t qsrc[3] = { sb + AT_QH, sb + AT_QL, sb + AT_QH };

    {
        float rc[2][4][4];
#pragma unroll
        for (int i = 0; i < 2; i++)
#pragma unroll
            for (int j = 0; j < 4; j++)
#pragma unroll
                for (int q = 0; q < 4; q++) rc[i][j][q] = 0.f;
        uint32_t rsrc[3] = { sb + AT_RH, sb + AT_RH, sb + AT_RL };
#pragma unroll
        for (int term = 0; term < 3; term++)
#pragma unroll
            for (int k16 = 0; k16 < 4; k16++) {
                uint32_t af[2][4];
#pragma unroll
                for (int mt = 0; mt < 2; mt++) {
                    int row = wm * 32 + mt * 16 + (lane & 15);
                    int col = k16 * 16 + (lane >> 4) * 8;
                    ldsm4(af[mt], qsrc[term] + (row * 72 + col) * 2);
                }
#pragma unroll
                for (int nq = 0; nq < 2; nq++) {
                    uint32_t bfr[4];
                    int n = wn * 32 + nq * 16 + ((lane >> 4) << 3) + (lane & 7);
                    int kc = k16 * 16 + ((lane >> 3) & 1) * 8;
                    ldsm4(bfr, rsrc[term] + (n * 72 + kc) * 2);
#pragma unroll
                    for (int mt = 0; mt < 2; mt++) {
                        mma16816(rc[mt][nq * 2],     af[mt], bfr[0], bfr[1]);
                        mma16816(rc[mt][nq * 2 + 1], af[mt], bfr[2], bfr[3]);
                    }
                }
            }
        float* LWH = reinterpret_cast<float*>(smc + AT_LWH);
#pragma unroll
        for (int mt = 0; mt < 2; mt++) {
            int r0 = wm * 32 + mt * 16 + (lane >> 2);
#pragma unroll
            for (int nf = 0; nf < 4; nf++) {
                int c = wn * 32 + nf * 8 + (lane & 3) * 2;
                LWH[r0 * 66 + c]       = rc[mt][nf][0];
                LWH[r0 * 66 + c + 1]   = rc[mt][nf][1];
                LWH[(r0 + 8) * 66 + c]     = rc[mt][nf][2];
                LWH[(r0 + 8) * 66 + c + 1] = rc[mt][nf][3];
            }
        }
    }
    __syncthreads();

    float acc[2][16][4];
#pragma unroll
    for (int i = 0; i < 2; i++)
#pragma unroll
        for (int j = 0; j < 16; j++)
#pragma unroll
            for (int q = 0; q < 4; q++) acc[i][j][q] = 0.f;
    {
        uint32_t ksrc[3] = { sb + AT_KH, sb + AT_KH, sb + AT_KL };
#pragma unroll
        for (int term = 0; term < 3; term++)
#pragma unroll
            for (int k16 = 0; k16 < 4; k16++) {
                uint32_t af[2][4];
#pragma unroll
                for (int mt = 0; mt < 2; mt++) {
                    int row = wm * 32 + mt * 16 + (lane & 15);
                    int col = k16 * 16 + (lane >> 4) * 8;
                    ldsm4(af[mt], qsrc[term] + (row * 72 + col) * 2);
                }
#pragma unroll
                for (int nq = 0; nq < 8; nq++) {
                    uint32_t bfr[4];
                    int n = wn * 128 + nq * 16 + ((lane >> 4) << 3) + (lane & 7);
                    int kc = k16 * 16 + ((lane >> 3) & 1) * 8;
                    ldsm4(bfr, ksrc[term] + (n * 72 + kc) * 2);
#pragma unroll
                    for (int mt = 0; mt < 2; mt++) {
                        mma16816(acc[mt][nq * 2],     af[mt], bfr[0], bfr[1]);
                        mma16816(acc[mt][nq * 2 + 1], af[mt], bfr[2], bfr[3]);
                    }
                }
            }
    }
    __syncthreads();

    {
        const __nv_bfloat16* vh = g_vTh + (size_t)bh * DHEAD * NKEY;
        const __nv_bfloat16* vl = g_vTl + (size_t)bh * DHEAD * NKEY;
#pragma unroll
        for (int i = 0; i < 8; i++) {
            int idx = i * 256 + t, row = idx >> 5, col = (idx & 31) * 8;
            cp16(sb + AT_VH + (row * 264 + col) * 2, vh + row * 256 + col);
            cp16(sb + AT_VL + (row * 264 + col) * 2, vl + row * 256 + col);
        }
        asm volatile("cp.async.commit_group;" ::: "memory");
    }

    float* LWH = reinterpret_cast<float*>(smc + AT_LWH);
    float* pm = reinterpret_cast<float*>(smc + AT_PM);
    float* ps = reinterpret_cast<float*>(smc + AT_PS);
    int r0t[2], r1t[2];
    float mx[2][2];
#pragma unroll
    for (int mt = 0; mt < 2; mt++) {
        r0t[mt] = wm * 32 + mt * 16 + (lane >> 2);
        r1t[mt] = r0t[mt] + 8;
        mx[mt][0] = -3.402823466e+38f; mx[mt][1] = -3.402823466e+38f;
        int wq80 = r0t[mt] >> 3, wq81 = r1t[mt] >> 3;
        const float* L0 = &LWH[r0t[mt] * 66];
        const float* L1 = &LWH[r1t[mt] * 66];
#pragma unroll
        for (int nf = 0; nf < 16; nf++) {
            int j = wn * 16 + nf;
            int hk = j >> 1;
            int c0 = (j & 1) * 8 + (lane & 3) * 2;
            float bh0 = L0[32 + hk - hq8 + 15];
            float bh1 = L1[32 + hk - hq8 + 15];
            float v0 = (acc[mt][nf][0] + bh0 + L0[c0 - wq80 + 15])     * 0.125f;
            float v1 = (acc[mt][nf][1] + bh0 + L0[c0 + 1 - wq80 + 15]) * 0.125f;
            float v2 = (acc[mt][nf][2] + bh1 + L1[c0 - wq81 + 15])     * 0.125f;
            float v3 = (acc[mt][nf][3] + bh1 + L1[c0 + 1 - wq81 + 15]) * 0.125f;
            acc[mt][nf][0] = v0; acc[mt][nf][1] = v1;
            acc[mt][nf][2] = v2; acc[mt][nf][3] = v3;
            mx[mt][0] = fmaxf(mx[mt][0], fmaxf(v0, v1));
            mx[mt][1] = fmaxf(mx[mt][1], fmaxf(v2, v3));
        }
#pragma unroll
        for (int o = 1; o <= 2; o <<= 1) {
            mx[mt][0] = fmaxf(mx[mt][0], __shfl_xor_sync(0xffffffffu, mx[mt][0], o));
            mx[mt][1] = fmaxf(mx[mt][1], __shfl_xor_sync(0xffffffffu, mx[mt][1], o));
        }
        pm[r0t[mt] * 2 + wn] = mx[mt][0];
        pm[r1t[mt] * 2 + wn] = mx[mt][1];
    }
    __syncthreads();
    float sum[2][2];
#pragma unroll
    for (int mt = 0; mt < 2; mt++) {
        float M0 = fmaxf(pm[r0t[mt] * 2], pm[r0t[mt] * 2 + 1]);
        float M1 = fmaxf(pm[r1t[mt] * 2], pm[r1t[mt] * 2 + 1]);
        sum[mt][0] = 0.f; sum[mt][1] = 0.f;
#pragma unroll
        for (int nf = 0; nf < 16; nf++) {
            float e0 = __expf(acc[mt][nf][0] - M0);
            float e1 = __expf(acc[mt][nf][1] - M0);
            float e2 = __expf(acc[mt][nf][2] - M1);
            float e3 = __expf(acc[mt][nf][3] - M1);
            acc[mt][nf][0] = e0; acc[mt][nf][1] = e1;
            acc[mt][nf][2] = e2; acc[mt][nf][3] = e3;
            sum[mt][0] += e0 + e1; sum[mt][1] += e2 + e3;
        }
#pragma unroll
        for (int o = 1; o <= 2; o <<= 1) {
            sum[mt][0] += __shfl_xor_sync(0xffffffffu, sum[mt][0], o);
            sum[mt][1] += __shfl_xor_sync(0xffffffffu, sum[mt][1], o);
        }
        ps[r0t[mt] * 2 + wn] = sum[mt][0];
        ps[r1t[mt] * 2 + wn] = sum[mt][1];
    }
    __syncthreads();

    size_t abase = ((size_t)bh * HW + (size_t)hq * 128) * NKEY;
    uint32_t uh[2][16], vh_[2][16], ul[2][16];
    uint32_t* vlS = reinterpret_cast<uint32_t*>(smc + AT_LWH) + t * 32;
#pragma unroll
    for (int mt = 0; mt < 2; mt++) {
        float inv0 = 1.f / (ps[r0t[mt] * 2] + ps[r0t[mt] * 2 + 1]);
        float inv1 = 1.f / (ps[r1t[mt] * 2] + ps[r1t[mt] * 2 + 1]);
#pragma unroll
        for (int nf = 0; nf < 16; nf++) {
            int j = wn * 16 + nf;
            int col = j * 8 + (lane & 3) * 2;
            float p0 = acc[mt][nf][0] * inv0, p1 = acc[mt][nf][1] * inv0;
            float p2 = acc[mt][nf][2] * inv1, p3 = acc[mt][nf][3] * inv1;
            *reinterpret_cast<float2*>(&attn_out[abase + (size_t)r0t[mt] * 256 + col]) =
                make_float2(p0, p1);
            *reinterpret_cast<float2*>(&attn_out[abase + (size_t)r1t[mt] * 256 + col]) =
                make_float2(p2, p3);
            uint32_t h01 = packbf(p0, p1), h23 = packbf(p2, p3);
            uh[mt][nf] = h01; vh_[mt][nf] = h23;
            __nv_bfloat162 hh01 = *reinterpret_cast<__nv_bfloat162*>(&h01);
            __nv_bfloat162 hh23 = *reinterpret_cast<__nv_bfloat162*>(&h23);
            ul[mt][nf] = packbf(p0 - __bfloat162float(hh01.x), p1 - __bfloat162float(hh01.y));
            vlS[mt * 16 + nf] = packbf(p2 - __bfloat162float(hh23.x), p3 - __bfloat162float(hh23.y));
        }
    }

    asm volatile("cp.async.wait_group 0;" ::: "memory");
    __syncthreads();
    float oacc[2][8][4];
#pragma unroll
    for (int i = 0; i < 2; i++)
#pragma unroll
        for (int j = 0; j < 8; j++)
#pragma unroll
            for (int q = 0; q < 4; q++) oacc[i][j][q] = 0.f;
#pragma unroll
    for (int kk = 0; kk < 8; kk++) {
        uint32_t afh[2][4], afl[2][4];
#pragma unroll
        for (int mt = 0; mt < 2; mt++) {
            afh[mt][0] = uh[mt][2 * kk];     afh[mt][1] = vh_[mt][2 * kk];
            afh[mt][2] = uh[mt][2 * kk + 1]; afh[mt][3] = vh_[mt][2 * kk + 1];
            afl[mt][0] = ul[mt][2 * kk];     afl[mt][1] = vlS[mt * 16 + 2 * kk];
            afl[mt][2] = ul[mt][2 * kk + 1]; afl[mt][3] = vlS[mt * 16 + 2 * kk + 1];
        }
        int kc = wn * 128 + kk * 16 + ((lane >> 3) & 1) * 8;
#pragma unroll
        for (int nq = 0; nq < 4; nq++) {
            int n = nq * 16 + ((lane >> 4) << 3) + (lane & 7);
            uint32_t bh_[4], bl_[4];
            ldsm4(bh_, sb + AT_VH + (n * 264 + kc) * 2);
            ldsm4(bl_, sb + AT_VL + (n * 264 + kc) * 2);
#pragma unroll
            for (int mt = 0; mt < 2; mt++) {
                mma16816(oacc[mt][nq * 2],     afh[mt], bh_[0], bh_[1]);
                mma16816(oacc[mt][nq * 2 + 1], afh[mt], bh_[2], bh_[3]);
                mma16816(oacc[mt][nq * 2],     afl[mt], bh_[0], bh_[1]);
                mma16816(oacc[mt][nq * 2 + 1], afl[mt], bh_[2], bh_[3]);
                mma16816(oacc[mt][nq * 2],     afh[mt], bl_[0], bl_[1]);
                mma16816(oacc[mt][nq * 2 + 1], afh[mt], bl_[2], bl_[3]);
            }
        }
    }

    float* oT = reinterpret_cast<float*>(smc + AT_LWH);   // [64][129]
    __syncthreads();
    if (wn == 0) {
#pragma unroll
        for (int mt = 0; mt < 2; mt++)
#pragma unroll
            for (int nf = 0; nf < 8; nf++) {
                int d = nf * 8 + (lane & 3) * 2;
                oT[d * 129 + r0t[mt]]       = oacc[mt][nf][0];
                oT[(d + 1) * 129 + r0t[mt]] = oacc[mt][nf][1];
                oT[d * 129 + r1t[mt]]       = oacc[mt][nf][2];
                oT[(d + 1) * 129 + r1t[mt]] = oacc[mt][nf][3];
            }
    }
    __syncthreads();
    if (wn == 1) {
#pragma unroll
        for (int mt = 0; mt < 2; mt++)
#pragma unroll
            for (int nf = 0; nf < 8; nf++) {
                int d = nf * 8 + (lane & 3) * 2;
                oT[d * 129 + r0t[mt]]       += oacc[mt][nf][0];
                oT[(d + 1) * 129 + r0t[mt]] += oacc[mt][nf][1];
                oT[d * 129 + r1t[mt]]       += oacc[mt][nf][2];
                oT[(d + 1) * 129 + r1t[mt]] += oacc[mt][nf][3];
            }
    }
    __syncthreads();
    for (int i = t; i < 64 * 128; i += 256) {
        int d = i >> 7, x = i & 127;
        g_y1[(((size_t)(b * CH + d * 4 + head)) * 128 + hq) * 128 + x] = oT[d * 129 + x];
    }
}

// ---------------------------------------------------------------------------
extern "C" void kernel_launch(void* const* d_in, const int* in_sizes, int n_in,
                              void* d_out, int out_size) {
    (void)in_sizes; (void)n_in; (void)out_size;
    const float* x    = (const float*)d_in[0];
    const float* dw1  = (const float*)d_in[1];
    const float* pw1  = (const float*)d_in[2];
    const float* relw = (const float*)d_in[3];
    const float* relh = (const float*)d_in[4];
    const float* dw2  = (const float*)d_in[5];
    const float* pw2  = (const float*)d_in[6];
    float* out  = (float*)d_out;
    float* attn = out + OUT_ELEMS;

    float* y2;
    cudaGetSymbolAddress((void**)&y2, g_y1);

    cudaFuncSetAttribute(attn_kernel, cudaFuncAttributeMaxDynamicSharedMemorySize, AT_SMEM);
    cudaFuncSetAttribute(gemm_mma_pw1, cudaFuncAttributeMaxDynamicSharedMemorySize, GEMM_SMEM);
    cudaFuncSetAttribute(gemm_mma_pw2, cudaFuncAttributeMaxDynamicSharedMemorySize, GEMM_SMEM);
    cudaFuncSetAttribute(dwt, cudaFuncAttributeMaxDynamicSharedMemorySize, DWT_SMEM);

    convert_w<<<1024, 256>>>(pw1, pw2);
    rel_build<<<16, 256>>>(relw, relh);
    dwt<<<dim3(16, 16, 4), 256, DWT_SMEM>>>(x, dw1, 0);
    gemm_mma_pw1<<<dim3(512, 6), 256, GEMM_SMEM>>>();
    pool_kv<<<2048, 256>>>();
    transpose_q<<<4096, 256>>>();
    attn_kernel<<<dim3(128, HEADS, BATCH), 256, AT_SMEM>>>(attn);
    dwt<<<dim3(16, 16, 4), 256, DWT_SMEM>>>(y2, dw2, 0);
    gemm_mma_pw2<<<dim3(512, 2), 256, GEMM_SMEM>>>(out);
}